// round 9
// baseline (speedup 1.0000x reference)
#include <cuda_runtime.h>
#include <cuda_bf16.h>
#include <cstdint>
#include <stdint.h>

#define NB 4
#define NC 64
#define NP 8192
#define KNBR 20
#define NPT (NB*NP)
#define NSAMP (NPT*KNBR)
#define FULLMASK 0xffffffffu

__device__ __align__(16) float g_f[NPT*NC];
__device__ float g_sq[NPT];
__device__ int   g_idx[NSAMP];
__device__ __align__(16) float g_P[NPT*NC];
__device__ __align__(16) float g_Q[NPT*NC];
__device__ float g_W1a[64*64];
__device__ float g_W1d[64*64];
__device__ float g_stats1[128];
__device__ float g_stats2[128];
__device__ float g_scale1[64], g_shift1[64];
__device__ float g_scale2[64], g_shift2[64];
__device__ __align__(16) float g_gmax[NPT*64];
__device__ __align__(16) float g_gmin[NPT*64];
// bf16 3-term split planes, [NPT][64] each, K-major
__device__ __align__(16) __nv_bfloat16 g_h1[NPT*64];
__device__ __align__(16) __nv_bfloat16 g_h2[NPT*64];
__device__ __align__(16) __nv_bfloat16 g_h3[NPT*64];

// ---------------- helpers (arch-neutral) ----------------
__device__ __forceinline__ uint32_t smem_u32(const void* p){
  uint32_t a;
  asm("{ .reg .u64 t; cvta.to.shared.u64 t, %1; cvt.u32.u64 %0, t; }" : "=r"(a) : "l"(p));
  return a;
}

// ---------------- prep ----------------
__global__ void k_prep(const float* __restrict__ W1){
  int o = blockIdx.x, c = threadIdx.x;
  float a  = W1[o*128 + c];
  float bb = W1[o*128 + 64 + c];
  g_W1a[o*64+c] = a;
  g_W1d[o*64+c] = bb - a;
  if(o == 0){
    g_stats1[c] = 0.f; g_stats1[64+c] = 0.f;
    g_stats2[c] = 0.f; g_stats2[64+c] = 0.f;
  }
}

// ---------------- transpose + sq + bf16 split ----------------
__global__ void k_transpose(const float* __restrict__ x){
  int b = blockIdx.y;
  int n = blockIdx.x*256 + threadIdx.x;
  const float* xb = x + b*NC*NP;
  int bn = b*NP + n;
  float4* f4 = reinterpret_cast<float4*>(g_f) + bn*16;
  __nv_bfloat162* o1 = reinterpret_cast<__nv_bfloat162*>(g_h1) + bn*32;
  __nv_bfloat162* o2 = reinterpret_cast<__nv_bfloat162*>(g_h2) + bn*32;
  __nv_bfloat162* o3 = reinterpret_cast<__nv_bfloat162*>(g_h3) + bn*32;
  float s = 0.f;
  #pragma unroll
  for(int c4=0; c4<16; c4++){
    float4 v;
    v.x = xb[(4*c4+0)*NP + n];
    v.y = xb[(4*c4+1)*NP + n];
    v.z = xb[(4*c4+2)*NP + n];
    v.w = xb[(4*c4+3)*NP + n];
    s += v.x*v.x + v.y*v.y + v.z*v.z + v.w*v.w;
    f4[c4] = v;
    float vv[4] = {v.x, v.y, v.z, v.w};
    __nv_bfloat16 a1[4], a2[4], a3[4];
    #pragma unroll
    for(int j=0;j<4;j++){
      float f = vv[j];
      __nv_bfloat16 t1 = __float2bfloat16_rn(f);
      float r1 = f - __bfloat162float(t1);
      __nv_bfloat16 t2 = __float2bfloat16_rn(r1);
      float r2 = r1 - __bfloat162float(t2);
      __nv_bfloat16 t3 = __float2bfloat16_rn(r2);
      a1[j]=t1; a2[j]=t2; a3[j]=t3;
    }
    __nv_bfloat162 p;
    p.x=a1[0]; p.y=a1[1]; o1[c4*2]=p;  p.x=a1[2]; p.y=a1[3]; o1[c4*2+1]=p;
    p.x=a2[0]; p.y=a2[1]; o2[c4*2]=p;  p.x=a2[2]; p.y=a2[3]; o2[c4*2+1]=p;
    p.x=a3[0]; p.y=a3[1]; o3[c4*2]=p;  p.x=a3[2]; p.y=a3[3]; o3[c4*2+1]=p;
  }
  g_sq[bn] = s;
}

// ---------------- knn kernel: tensor path (sm_103a) or scalar fallback ----------------
#define KN_TMEMPTR 0
#define KN_MBAR    8
#define KN_B0      1024
#define KN_TILE    49152
#define KN_B1      (KN_B0 + KN_TILE)      // 50176
#define KN_SQ      (KN_B1 + KN_TILE)      // 99328
#define KN_SMEM    (KN_SQ + 1024)         // 100352
#define KN_IDESC   0x8200490u   // f32 acc, bf16 x bf16 K-major, N=128, M=128
#define TM_A       0            // A: 96 cols (3 chunks x 32)
#define TM_D       128          // D: 128 cols
#define TM_COLS    256

#if defined(__CUDA_ARCH__) && defined(__CUDA_ARCH_FEAT_SM103_ALL)
__device__ __forceinline__ uint32_t elect_one(){
  uint32_t p;
  asm volatile("{\n\t.reg .pred p;\n\telect.sync _|p, 0xFFFFFFFF;\n\tselp.b32 %0, 1, 0, p;\n\t}" : "=r"(p));
  return p;
}
// TS-mode f16 MMA: A in TMEM, B via SMEM descriptor
__device__ __forceinline__ void mma_f16_ts(uint32_t d, uint32_t a_tmem, uint64_t bd, uint32_t idesc, uint32_t en){
  asm volatile(
    "{\n\t.reg .pred p;\n\tsetp.ne.u32 p, %4, 0;\n\t"
    "tcgen05.mma.cta_group::1.kind::f16 [%0], [%1], %2, %3, {%5,%5,%5,%5}, p;\n\t}"
    :: "r"(d), "r"(a_tmem), "l"(bd), "r"(idesc), "r"(en), "r"(0u) : "memory");
}
// GENUINE poll: mbarrier.test_wait is non-blocking (unlike try_wait, which
// blocks for a system-dependent limit even WITHOUT a suspend hint — that was
// the 40ms mystery: warps slept to timeout because the async-proxy arrival
// from tcgen05.commit doesn't produce a prompt wakeup).
__device__ __forceinline__ void mbar_wait(uint32_t mbar, uint32_t parity){
  asm volatile(
    "{\n\t.reg .pred P1;\n\t"
    "WL%=:\n\t"
    "mbarrier.test_wait.parity.acquire.cta.shared::cta.b64 P1, [%0], %1;\n\t"
    "@!P1 bra.uni WL%=;\n\t"
    "}"
    :: "r"(mbar), "r"(parity) : "memory");
}
#define LDTM16(r, addr) \
  asm volatile("tcgen05.ld.sync.aligned.32x32b.x16.b32 " \
    "{%0,%1,%2,%3,%4,%5,%6,%7,%8,%9,%10,%11,%12,%13,%14,%15}, [%16];" \
    : "=r"((r)[0]),"=r"((r)[1]),"=r"((r)[2]),"=r"((r)[3]),"=r"((r)[4]),"=r"((r)[5]),"=r"((r)[6]),"=r"((r)[7]), \
      "=r"((r)[8]),"=r"((r)[9]),"=r"((r)[10]),"=r"((r)[11]),"=r"((r)[12]),"=r"((r)[13]),"=r"((r)[14]),"=r"((r)[15]) \
    : "r"(addr))
#define STTM32(addr, r) \
  asm volatile("tcgen05.st.sync.aligned.32x32b.x32.b32 [%0], " \
    "{%1,%2,%3,%4,%5,%6,%7,%8,%9,%10,%11,%12,%13,%14,%15,%16," \
    "%17,%18,%19,%20,%21,%22,%23,%24,%25,%26,%27,%28,%29,%30,%31,%32};" \
    :: "r"(addr), \
       "r"((r)[0]),"r"((r)[1]),"r"((r)[2]),"r"((r)[3]),"r"((r)[4]),"r"((r)[5]),"r"((r)[6]),"r"((r)[7]), \
       "r"((r)[8]),"r"((r)[9]),"r"((r)[10]),"r"((r)[11]),"r"((r)[12]),"r"((r)[13]),"r"((r)[14]),"r"((r)[15]), \
       "r"((r)[16]),"r"((r)[17]),"r"((r)[18]),"r"((r)[19]),"r"((r)[20]),"r"((r)[21]),"r"((r)[22]),"r"((r)[23]), \
       "r"((r)[24]),"r"((r)[25]),"r"((r)[26]),"r"((r)[27]),"r"((r)[28]),"r"((r)[29]),"r"((r)[30]),"r"((r)[31]) \
    : "memory")
#define TC_WAIT_LD()  asm volatile("tcgen05.wait::ld.sync.aligned;" ::: "memory")
#define TC_WAIT_ST()  asm volatile("tcgen05.wait::st.sync.aligned;" ::: "memory")
#define TC_FENCE_BEFORE() asm volatile("tcgen05.fence::before_thread_sync;" ::: "memory")
#define TC_FENCE_AFTER()  asm volatile("tcgen05.fence::after_thread_sync;" ::: "memory")
#define FENCE_ASYNC() asm volatile("fence.proxy.async.shared::cta;" ::: "memory")
#define CP_COMMIT() asm volatile("cp.async.commit_group;" ::: "memory")
#define CP_WAIT0()  asm volatile("cp.async.wait_group 0;" ::: "memory")

static constexpr uint64_t DESC_BASE_SW128 =
    (uint64_t(2)  << 61) | (uint64_t(1) << 46) | (uint64_t(64) << 32) | (uint64_t(1) << 16);
__device__ __forceinline__ uint64_t make_desc(uint32_t addr){
  return DESC_BASE_SW128 | ((uint64_t)(addr >> 4) & 0x3FFF);
}

__device__ __forceinline__ void load_tile_cp(uint32_t sb_dst, const uint4* p0, const uint4* p1, const uint4* p2, int t){
  #pragma unroll
  for(int i=0;i<12;i++){
    int chunk = i >> 2;
    int rem = ((i&3)<<8) + t;
    int row = rem >> 3;
    int col = rem & 7;
    const uint4* src = (chunk==0? p0 : (chunk==1? p1 : p2)) + row*8 + col;
    uint32_t boff = (uint32_t)((row<<7) + (col<<4));
    uint32_t dst = sb_dst + chunk*16384 + (boff ^ ((boff>>3)&0x70));
    asm volatile("cp.async.cg.shared.global [%0], [%1], 16;" :: "r"(dst), "l"(src) : "memory");
  }
}

#define INSERT(vv, ii) do{ \
  if((vv) < worst){ \
    bool done=false; \
    _Pragma("unroll") \
    for(int _s=0;_s<KNBR;_s++){ \
      if(!done && kd[_s]==worst){ kd[_s]=(vv); ki[_s]=(ii); done=true; } \
    } \
    worst = kd[0]; \
    _Pragma("unroll") \
    for(int _s=1;_s<KNBR;_s++) worst = fmaxf(worst, kd[_s]); \
  } \
}while(0)

#define SEL16(dr, jb, gcol) do{ \
  float vv[16]; \
  _Pragma("unroll") \
  for(int _j=0;_j<16;_j++) \
    vv[_j] = fmaf(-2.f, __uint_as_float((dr)[_j]), __shfl_sync(FULLMASK, sqcv, (jb)+_j)); \
  float _mn = vv[0]; \
  _Pragma("unroll") \
  for(int _j=1;_j<16;_j++) _mn = fminf(_mn, vv[_j]); \
  if(__any_sync(FULLMASK, _mn < worst)){ \
    _Pragma("unroll") \
    for(int _j=0;_j<16;_j++) INSERT(vv[_j], (gcol)+(jb)+_j); \
  } \
}while(0)
#endif // feature guard

// scalar fallback worker: one 64-row R2-style pass
__device__ void knn_scalar_pass(char* smemc, int b, int rbase){
  float (*sA)[68] = reinterpret_cast<float(*)[68]>(smemc);
  float (*sB)[68] = reinterpret_cast<float(*)[68]>(smemc + 17408);
  float* sqr = reinterpret_cast<float*>(smemc + 34816);
  float* sqc = reinterpret_cast<float*>(smemc + 34816 + 256);
  float* sD = &sB[0][0];
  int t = threadIdx.x;
  int lane = t & 31, warp = t >> 5;
  const float INF = __int_as_float(0x7f800000);

  __syncthreads();
  {
    int r = t>>2, cq = (t&3)*4;
    const float4* fr = reinterpret_cast<const float4*>(g_f) + (b*NP + rbase + r)*16;
    #pragma unroll
    for(int j=0;j<4;j++){
      float4 v = fr[cq+j];
      int c = (cq+j)*4;
      sA[c+0][r]=v.x; sA[c+1][r]=v.y; sA[c+2][r]=v.z; sA[c+3][r]=v.w;
    }
    if(t < 64) sqr[t] = g_sq[b*NP + rbase + t];
  }

  float kd[8]; int ki[8]; float worst[8];
  #pragma unroll
  for(int j=0;j<8;j++){ kd[j]=INF; ki[j]=0; worst[j]=INF; }

  int ty = t>>4, tx = t&15;
  for(int ct=0; ct<NP/64; ct++){
    __syncthreads();
    {
      int r = t>>2, cq = (t&3)*4;
      const float4* fr = reinterpret_cast<const float4*>(g_f) + (b*NP + ct*64 + r)*16;
      #pragma unroll
      for(int j=0;j<4;j++){
        float4 v = fr[cq+j];
        int c = (cq+j)*4;
        sB[c+0][r]=v.x; sB[c+1][r]=v.y; sB[c+2][r]=v.z; sB[c+3][r]=v.w;
      }
      if(t < 64) sqc[t] = g_sq[b*NP + ct*64 + t];
    }
    __syncthreads();
    float acc[4][4];
    #pragma unroll
    for(int i=0;i<4;i++)
      #pragma unroll
      for(int j=0;j<4;j++) acc[i][j]=0.f;
    #pragma unroll 4
    for(int c=0;c<64;c++){
      float4 a = *reinterpret_cast<const float4*>(&sA[c][ty*4]);
      float4 w = *reinterpret_cast<const float4*>(&sB[c][tx*4]);
      acc[0][0]+=a.x*w.x; acc[0][1]+=a.x*w.y; acc[0][2]+=a.x*w.z; acc[0][3]+=a.x*w.w;
      acc[1][0]+=a.y*w.x; acc[1][1]+=a.y*w.y; acc[1][2]+=a.y*w.z; acc[1][3]+=a.y*w.w;
      acc[2][0]+=a.z*w.x; acc[2][1]+=a.z*w.y; acc[2][2]+=a.z*w.z; acc[2][3]+=a.z*w.w;
      acc[3][0]+=a.w*w.x; acc[3][1]+=a.w*w.y; acc[3][2]+=a.w*w.z; acc[3][3]+=a.w*w.w;
    }
    __syncthreads();
    #pragma unroll
    for(int i=0;i<4;i++){
      int r = ty*4 + i;
      float4 d;
      d.x = sqr[r] + sqc[tx*4+0] - 2.f*acc[i][0];
      d.y = sqr[r] + sqc[tx*4+1] - 2.f*acc[i][1];
      d.z = sqr[r] + sqc[tx*4+2] - 2.f*acc[i][2];
      d.w = sqr[r] + sqc[tx*4+3] - 2.f*acc[i][3];
      *reinterpret_cast<float4*>(&sD[r*68 + tx*4]) = d;
    }
    __syncthreads();

    int base = ct*64;
    #pragma unroll
    for(int j=0;j<8;j++){
      int r = warp*8 + j;
      float d0 = sD[r*68 + lane];
      float d1 = sD[r*68 + 32 + lane];
      float w = worst[j];
      unsigned m0 = __ballot_sync(FULLMASK, d0 < w);
      unsigned m1 = __ballot_sync(FULLMASK, d1 < w);
      while(m0 | m1){
        float cd; int cm;
        if(m0){ int src=__ffs(m0)-1; m0 &= m0-1; cd=__shfl_sync(FULLMASK,d0,src); cm=base+src; }
        else  { int src=__ffs(m1)-1; m1 &= m1-1; cd=__shfl_sync(FULLMASK,d1,src); cm=base+32+src; }
        float bv = (lane < KNBR) ? kd[j] : -INF;
        int bl = lane;
        #pragma unroll
        for(int off=16; off; off>>=1){
          float ov = __shfl_xor_sync(FULLMASK, bv, off);
          int   ol = __shfl_xor_sync(FULLMASK, bl, off);
          if(ov > bv || (ov == bv && ol < bl)){ bv = ov; bl = ol; }
        }
        if(cd < bv && lane == bl){ kd[j] = cd; ki[j] = cm; }
      }
      float bv = (lane < KNBR) ? kd[j] : -INF;
      #pragma unroll
      for(int off=16; off; off>>=1) bv = fmaxf(bv, __shfl_xor_sync(FULLMASK, bv, off));
      worst[j] = bv;
    }
  }
  #pragma unroll
  for(int j=0;j<8;j++){
    int r = warp*8 + j;
    if(lane < KNBR) g_idx[(b*NP + rbase + r)*KNBR + lane] = ki[j];
  }
}

__global__ __launch_bounds__(256, 2) void k_knn_tc(){
  extern __shared__ char smem[];
  int t = threadIdx.x;
  int b = blockIdx.y;
  int rbase = blockIdx.x*128;

#if defined(__CUDA_ARCH__) && defined(__CUDA_ARCH_FEAT_SM103_ALL)
  uint32_t sb = smem_u32(smem);
  int lane = t & 31, wid = t >> 5;

  if(wid == 0){
    asm volatile("tcgen05.alloc.cta_group::1.sync.aligned.shared::cta.b32 [%0], %1;"
                 :: "r"(sb + KN_TMEMPTR), "r"((uint32_t)TM_COLS) : "memory");
    asm volatile("tcgen05.relinquish_alloc_permit.cta_group::1.sync.aligned;");
  }
  if(t == 0){
    asm volatile("mbarrier.init.shared.b64 [%0], %1;" :: "r"(sb+KN_MBAR), "r"(1u) : "memory");
  }
  __syncthreads();
  uint32_t tbase;
  asm volatile("ld.shared.b32 %0, [%1];" : "=r"(tbase) : "r"(sb + KN_TMEMPTR));

  const uint4* P1 = reinterpret_cast<const uint4*>(g_h1);
  const uint4* P2 = reinterpret_cast<const uint4*>(g_h2);
  const uint4* P3 = reinterpret_cast<const uint4*>(g_h3);
  float* sqcb = reinterpret_cast<float*>(smem + KN_SQ);

  // ---- A -> TMEM (warps 0-3; thread t<128 owns A-row t) ----
  if(t < 128){
    uint32_t warp_off = ((uint32_t)(t>>5)) << 21;
    long rowbase = (long)(b*NP + rbase + t)*8;   // uint4 index of row start (per plane)
    #pragma unroll
    for(int chunk=0; chunk<3; chunk++){
      const uint4* src = (chunk==0? P1 : (chunk==1? P2 : P3)) + rowbase;
      uint32_t a[32];
      #pragma unroll
      for(int q=0;q<8;q++){
        uint4 v = src[q];
        a[q*4+0]=v.x; a[q*4+1]=v.y; a[q*4+2]=v.z; a[q*4+3]=v.w;
      }
      STTM32(tbase + TM_A + chunk*32 + warp_off, a);
    }
    TC_WAIT_ST();
  }
  TC_FENCE_BEFORE();

  // ---- prologue: load B tile 0 ----
  {
    long roff = (long)(b*NP)*8;
    load_tile_cp(sb + KN_B0, P1 + roff, P2 + roff, P3 + roff, t);
    if(t < 128) sqcb[t] = g_sq[b*NP + t];
  }
  CP_COMMIT();
  __syncthreads();

  // top-k state
  float kd[KNBR]; int ki[KNBR]; float worst;
  const float INF = __int_as_float(0x7f800000);
  #pragma unroll
  for(int s=0;s<KNBR;s++){ kd[s]=INF; ki[s]=0; }
  worst = INF;

  const int pa[6] = {0,0,1,1,0,2};
  const int pb[6] = {0,1,0,1,2,0};
  int half = wid >> 2;

  for(int ct=0; ct<NP/128; ct++){
    int buf = ct & 1;
    // B[buf] for tile ct in flight; drain + make visible to async proxy
    CP_WAIT0(); FENCE_ASYNC();
    __syncthreads();   // also closes prev selection's sqcb reads before the next overwrite below

    // issue TS MMA batch -> D, commit
    if(wid == 0){
      TC_FENCE_AFTER();
      if(elect_one()){
        uint64_t bdesc = make_desc(sb + (buf ? KN_B1 : KN_B0));
        int first = 1;
        #pragma unroll
        for(int pr=0; pr<6; pr++){
          #pragma unroll
          for(int sub=0; sub<4; sub++){
            mma_f16_ts(tbase + TM_D,
                       tbase + TM_A + (uint32_t)(pa[pr]*32 + sub*8),
                       bdesc + (uint64_t)(pb[pr]*1024 + sub*2),
                       KN_IDESC, first ? 0u : 1u);
            first = 0;
          }
        }
        asm volatile("tcgen05.commit.cta_group::1.mbarrier::arrive::one.shared::cluster.b64 [%0];"
                     :: "r"(sb+KN_MBAR) : "memory");
      }
    }

    // overlap: prefetch B for tile ct+1 into the other buffer
    if(ct + 1 < NP/128){
      long roff = (long)(b*NP + (ct+1)*128)*8;
      load_tile_cp(sb + (buf ? KN_B0 : KN_B1), P1 + roff, P2 + roff, P3 + roff, t);
      if(t < 128) sqcb[(buf^1)*128 + t] = g_sq[b*NP + (ct+1)*128 + t];
    }
    CP_COMMIT();

    // wait for MMA completion (phase ct) — genuine poll via test_wait
    mbar_wait(sb + KN_MBAR, (uint32_t)(ct & 1));
    TC_FENCE_AFTER();

    // selection from D
    {
      int gbase = ct*128;
      #pragma unroll
      for(int h=0; h<2; h++){
        int chunk = half + h*2;
        float sqcv = sqcb[buf*128 + chunk*32 + lane];
        int gcol = gbase + chunk*32;
        uint32_t dr[16];
        LDTM16(dr, tbase + TM_D + chunk*32);
        TC_WAIT_LD();
        SEL16(dr, 0, gcol);
        LDTM16(dr, tbase + TM_D + chunk*32 + 16);
        TC_WAIT_LD();
        SEL16(dr, 16, gcol);
      }
      TC_FENCE_BEFORE();
    }
  }
  __syncthreads();

  // merge halves (reuse B0 region)
  float* mv = reinterpret_cast<float*>(smem + KN_B0);
  int*   mi = reinterpret_cast<int*>(smem + KN_B0 + 128*40*4);
  {
    int rloc = ((wid&3)<<5) + lane;
    int off = rloc*40 + half*20;
    #pragma unroll
    for(int s=0;s<KNBR;s++){ mv[off+s]=kd[s]; mi[off+s]=ki[s]; }
  }
  __syncthreads();
  if(t < 128){
    float* pv = mv + t*40;
    int*   pi = mi + t*40;
    int obase = (b*NP + rbase + t)*KNBR;
    for(int k=0;k<KNBR;k++){
      float best = pv[0]; int bj = 0;
      #pragma unroll 8
      for(int j=1;j<40;j++){ float u = pv[j]; if(u < best){ best = u; bj = j; } }
      g_idx[obase + k] = pi[bj];
      pv[bj] = INF;
    }
  }
  __syncthreads();
  if(t == 0){
    asm volatile("mbarrier.inval.shared.b64 [%0];" :: "r"(sb+KN_MBAR) : "memory");
  }
  __syncthreads();
  if(wid == 0){
    asm volatile("tcgen05.dealloc.cta_group::1.sync.aligned.b32 %0, %1;"
                 :: "r"(tbase), "r"((uint32_t)TM_COLS));
  }
#else
  // scalar fallback: two 64-row passes (non-a target)
  knn_scalar_pass(smem, b, rbase);
  knn_scalar_pass(smem, b, rbase + 64);
  (void)t;
#endif
}

// ---------------- P/Q gemms ----------------
__global__ __launch_bounds__(256) void k_gemm64(int which){
  __shared__ float sA[64][68];
  __shared__ float sW[64][68];
  const float* __restrict__ Wm = which ? g_W1d : g_W1a;
  float* __restrict__ Out = which ? g_Q : g_P;
  int t = threadIdx.x;
  int b = blockIdx.y; int rbase = blockIdx.x*64;
  {
    int r = t>>2, cq = (t&3)*4;
    const float4* fr = reinterpret_cast<const float4*>(g_f) + (b*NP + rbase + r)*16;
    #pragma unroll
    for(int j=0;j<4;j++){
      float4 v = fr[cq+j];
      int c = (cq+j)*4;
      sA[c+0][r]=v.x; sA[c+1][r]=v.y; sA[c+2][r]=v.z; sA[c+3][r]=v.w;
    }
  }
  for(int i=t;i<4096;i+=256){ int o=i>>6, c=i&63; sW[c][o] = Wm[o*64+c]; }
  __syncthreads();
  int ty=t>>4, tx=t&15;
  float acc[4][4];
  #pragma unroll
  for(int i=0;i<4;i++)
    #pragma unroll
    for(int j=0;j<4;j++) acc[i][j]=0.f;
  #pragma unroll 4
  for(int c=0;c<64;c++){
    float4 a = *reinterpret_cast<const float4*>(&sA[c][ty*4]);
    float4 w = *reinterpret_cast<const float4*>(&sW[c][tx*4]);
    acc[0][0]+=a.x*w.x; acc[0][1]+=a.x*w.y; acc[0][2]+=a.x*w.z; acc[0][3]+=a.x*w.w;
    acc[1][0]+=a.y*w.x; acc[1][1]+=a.y*w.y; acc[1][2]+=a.y*w.z; acc[1][3]+=a.y*w.w;
    acc[2][0]+=a.z*w.x; acc[2][1]+=a.z*w.y; acc[2][2]+=a.z*w.z; acc[2][3]+=a.z*w.w;
    acc[3][0]+=a.w*w.x; acc[3][1]+=a.w*w.y; acc[3][2]+=a.w*w.z; acc[3][3]+=a.w*w.w;
  }
  float4* O4 = reinterpret_cast<float4*>(Out) + (b*NP + rbase)*16;
  #pragma unroll
  for(int i=0;i<4;i++)
    O4[(ty*4+i)*16 + tx] = make_float4(acc[i][0],acc[i][1],acc[i][2],acc[i][3]);
}

// ---------------- BN1 stats ----------------
__global__ __launch_bounds__(256) void k_stats1(){
  __shared__ float r1[4][64];
  __shared__ float r2[4][64];
  int t = threadIdx.x;
  int o = t & 63, sub = t >> 6;
  int base = blockIdx.x * 512;
  float s1 = 0.f, s2 = 0.f;
  for(int i = sub; i < 512; i += 4){
    int s = base + i;
    int bn = s / KNBR;
    int b = bn >> 13;
    int m = g_idx[s];
    float h = g_P[((b<<13)+m)*64 + o] + g_Q[bn*64 + o];
    s1 += h; s2 += h*h;
  }
  r1[sub][o] = s1; r2[sub][o] = s2;
  __syncthreads();
  if(sub == 0){
    atomicAdd(&g_stats1[o],    r1[0][o]+r1[1][o]+r1[2][o]+r1[3][o]);
    atomicAdd(&g_stats1[64+o], r2[0][o]+r2[1][o]+r2[2][o]+r2[3][o]);
  }
}

// ---------------- BN finalize ----------------
__global__ void k_bnfin(const float* __restrict__ g, const float* __restrict__ bb, int which){
  int o = threadIdx.x;
  const float* stats = which ? g_stats2 : g_stats1;
  const float inv = 1.f/(float)NSAMP;
  float mu  = stats[o]*inv;
  float var = stats[64+o]*inv - mu*mu;
  float rstd = rsqrtf(var + 1e-5f);
  float sc = g[o]*rstd;
  if(which){ g_scale2[o]=sc; g_shift2[o]=bb[o]-mu*sc; }
  else     { g_scale1[o]=sc; g_shift1[o]=bb[o]-mu*sc; }
}

// ---------------- conv2 + BN2 stats + max/min over k ----------------
#define PTS_PER 16
__global__ __launch_bounds__(256) void k_conv2(const float* __restrict__ W2){
  __shared__ float sA[64][68];
  __shared__ float sW[64][68];
  __shared__ float sScale[64], sShift[64];
  __shared__ float r1[4][64];
  __shared__ float r2[4][64];
  int t = threadIdx.x;
  const float INF = __int_as_float(0x7f800000);

  for(int i=t;i<4096;i+=256){ int o=i>>6, c=i&63; sW[c][o] = W2[o*64+c]; }
  if(t < 64){ sScale[t]=g_scale1[t]; sShift[t]=g_shift1[t]; }

  float ls1 = 0.f, ls2 = 0.f;
  float rmax[4], rmin[4];
  #pragma unroll
  for(int q=0;q<4;q++){ rmax[q]=-INF; rmin[q]=INF; }

  int ty=t>>4, tx=t&15;
  int myo = t & 63;
  int Sbase = blockIdx.x * (PTS_PER*KNBR);
  int pbase = blockIdx.x * PTS_PER;
  float* sH = &sA[0][0];

  for(int st=0; st<5; st++){
    __syncthreads();
    {
      int sl = t>>2, cq = (t&3)*4;
      int s = Sbase + st*64 + sl;
      int bn = s / KNBR;
      int b = bn >> 13;
      int m = g_idx[s];
      const float4* Pm = reinterpret_cast<const float4*>(g_P) + ((b<<13)+m)*16;
      const float4* Qn = reinterpret_cast<const float4*>(g_Q) + bn*16;
      #pragma unroll
      for(int j=0;j<4;j++){
        int cc = (cq+j)*4;
        float4 p = Pm[cq+j]; float4 q = Qn[cq+j];
        float v0=(p.x+q.x)*sScale[cc+0]+sShift[cc+0]; v0 = v0>=0.f? v0 : 0.2f*v0;
        float v1=(p.y+q.y)*sScale[cc+1]+sShift[cc+1]; v1 = v1>=0.f? v1 : 0.2f*v1;
        float v2=(p.z+q.z)*sScale[cc+2]+sShift[cc+2]; v2 = v2>=0.f? v2 : 0.2f*v2;
        float v3=(p.w+q.w)*sScale[cc+3]+sShift[cc+3]; v3 = v3>=0.f? v3 : 0.2f*v3;
        sA[cc+0][sl]=v0; sA[cc+1][sl]=v1; sA[cc+2][sl]=v2; sA[cc+3][sl]=v3;
      }
    }
    __syncthreads();

    float acc[4][4];
    #pragma unroll
    for(int i=0;i<4;i++)
      #pragma unroll
      for(int j=0;j<4;j++) acc[i][j]=0.f;
    #pragma unroll 4
    for(int c=0;c<64;c++){
      float4 a = *reinterpret_cast<const float4*>(&sA[c][ty*4]);
      float4 w = *reinterpret_cast<const float4*>(&sW[c][tx*4]);
      acc[0][0]+=a.x*w.x; acc[0][1]+=a.x*w.y; acc[0][2]+=a.x*w.z; acc[0][3]+=a.x*w.w;
      acc[1][0]+=a.y*w.x; acc[1][1]+=a.y*w.y; acc[1][2]+=a.y*w.z; acc[1][3]+=a.y*w.w;
      acc[2][0]+=a.z*w.x; acc[2][1]+=a.z*w.y; acc[2][2]+=a.z*w.z; acc[2][3]+=a.z*w.w;
      acc[3][0]+=a.w*w.x; acc[3][1]+=a.w*w.y; acc[3][2]+=a.w*w.z; acc[3][3]+=a.w*w.w;
    }
    __syncthreads();
    #pragma unroll
    for(int i=0;i<4;i++)
      #pragma unroll
      for(int j=0;j<4;j++)
        sH[(tx*4+j)*68 + ty*4+i] = acc[i][j];
    __syncthreads();
    #pragma unroll
    for(int q=0;q<4;q++){
      int p = (t>>6) + q*4;
      int s0 = p*KNBR - st*64;
      int s1e = s0 + KNBR;
      if(s0 < 0) s0 = 0;
      if(s1e > 64) s1e = 64;
      float mx = rmax[q], mn = rmin[q];
      for(int s=s0; s<s1e; s++){
        float v = sH[myo*68 + s];
        ls1 += v; ls2 += v*v;
        mx = fmaxf(mx, v); mn = fminf(mn, v);
      }
      rmax[q] = mx; rmin[q] = mn;
    }
  }

  #pragma unroll
  for(int q=0;q<4;q++){
    int p = (t>>6) + q*4;
    g_gmax[(pbase+p)*64 + myo] = rmax[q];
    g_gmin[(pbase+p)*64 + myo] = rmin[q];
  }
  r1[t>>6][myo] = ls1;
  r2[t>>6][myo] = ls2;
  __syncthreads();
  if(t < 64){
    atomicAdd(&g_stats2[t],    r1[0][t]+r1[1][t]+r1[2][t]+r1[3][t]);
    atomicAdd(&g_stats2[64+t], r2[0][t]+r2[1][t]+r2[2][t]+r2[3][t]);
  }
}

// ---------------- output ----------------
__global__ void k_out(float* __restrict__ out){
  int n = blockIdx.x*256 + threadIdx.x;
  int o = blockIdx.y, b = blockIdx.z;
  float s = g_scale2[o], tsh = g_shift2[o];
  const float* src = (s >= 0.f) ? g_gmax : g_gmin;
  float v = src[(b*NP + n)*64 + o];
  float h = s*v + tsh;
  out[(b*64 + o)*NP + n] = (h >= 0.f) ? h : 0.2f*h;
}

extern "C" void kernel_launch(void* const* d_in, const int* in_sizes, int n_in,
                              void* d_out, int out_size){
  const float* x  = (const float*)d_in[0];
  const float* W1 = (const float*)d_in[1];
  const float* g1 = (const float*)d_in[2];
  const float* b1 = (const float*)d_in[3];
  const float* W2 = (const float*)d_in[4];
  const float* g2 = (const float*)d_in[5];
  const float* b2 = (const float*)d_in[6];
  float* out = (float*)d_out;

  cudaFuncSetAttribute(k_knn_tc, cudaFuncAttributeMaxDynamicSharedMemorySize, KN_SMEM);

  k_prep<<<64, 64>>>(W1);
  k_transpose<<<dim3(NP/256, NB), 256>>>(x);
  k_gemm64<<<dim3(NP/64, NB), 256>>>(0);
  k_gemm64<<<dim3(NP/64, NB), 256>>>(1);
  k_knn_tc<<<dim3(NP/128, NB), 256, KN_SMEM>>>();
  k_stats1<<<NSAMP/512, 256>>>();
  k_bnfin<<<1, 64>>>(g1, b1, 0);
  k_conv2<<<NPT/PTS_PER, 256>>>(W2);
  k_bnfin<<<1, 64>>>(g2, b2, 1);
  k_out<<<dim3(NP/256, 64, NB), 256>>>(out);
}

// round 10
// speedup vs baseline: 1.0009x; 1.0009x over previous
#include <cuda_runtime.h>
#include <cuda_bf16.h>
#include <cstdint>
#include <stdint.h>

#define NB 4
#define NC 64
#define NP 8192
#define KNBR 20
#define NPT (NB*NP)
#define NSAMP (NPT*KNBR)
#define FULLMASK 0xffffffffu

__device__ __align__(16) float g_f[NPT*NC];
__device__ float g_sq[NPT];
__device__ int   g_idx[NSAMP];
__device__ __align__(16) float g_P[NPT*NC];
__device__ __align__(16) float g_Q[NPT*NC];
__device__ float g_W1a[64*64];
__device__ float g_W1d[64*64];
__device__ float g_stats1[128];
__device__ float g_stats2[128];
__device__ float g_scale1[64], g_shift1[64];
__device__ float g_scale2[64], g_shift2[64];
__device__ __align__(16) float g_gmax[NPT*64];
__device__ __align__(16) float g_gmin[NPT*64];
// bf16 3-term split planes, [NPT][64] each, K-major
__device__ __align__(16) __nv_bfloat16 g_h1[NPT*64];
__device__ __align__(16) __nv_bfloat16 g_h2[NPT*64];
__device__ __align__(16) __nv_bfloat16 g_h3[NPT*64];

// ---------------- helpers (arch-neutral) ----------------
__device__ __forceinline__ uint32_t smem_u32(const void* p){
  uint32_t a;
  asm("{ .reg .u64 t; cvta.to.shared.u64 t, %1; cvt.u32.u64 %0, t; }" : "=r"(a) : "l"(p));
  return a;
}

// ---------------- prep ----------------
__global__ void k_prep(const float* __restrict__ W1){
  int o = blockIdx.x, c = threadIdx.x;
  float a  = W1[o*128 + c];
  float bb = W1[o*128 + 64 + c];
  g_W1a[o*64+c] = a;
  g_W1d[o*64+c] = bb - a;
  if(o == 0){
    g_stats1[c] = 0.f; g_stats1[64+c] = 0.f;
    g_stats2[c] = 0.f; g_stats2[64+c] = 0.f;
  }
}

// ---------------- transpose + sq + bf16 split ----------------
__global__ void k_transpose(const float* __restrict__ x){
  int b = blockIdx.y;
  int n = blockIdx.x*256 + threadIdx.x;
  const float* xb = x + b*NC*NP;
  int bn = b*NP + n;
  float4* f4 = reinterpret_cast<float4*>(g_f) + bn*16;
  __nv_bfloat162* o1 = reinterpret_cast<__nv_bfloat162*>(g_h1) + bn*32;
  __nv_bfloat162* o2 = reinterpret_cast<__nv_bfloat162*>(g_h2) + bn*32;
  __nv_bfloat162* o3 = reinterpret_cast<__nv_bfloat162*>(g_h3) + bn*32;
  float s = 0.f;
  #pragma unroll
  for(int c4=0; c4<16; c4++){
    float4 v;
    v.x = xb[(4*c4+0)*NP + n];
    v.y = xb[(4*c4+1)*NP + n];
    v.z = xb[(4*c4+2)*NP + n];
    v.w = xb[(4*c4+3)*NP + n];
    s += v.x*v.x + v.y*v.y + v.z*v.z + v.w*v.w;
    f4[c4] = v;
    float vv[4] = {v.x, v.y, v.z, v.w};
    __nv_bfloat16 a1[4], a2[4], a3[4];
    #pragma unroll
    for(int j=0;j<4;j++){
      float f = vv[j];
      __nv_bfloat16 t1 = __float2bfloat16_rn(f);
      float r1 = f - __bfloat162float(t1);
      __nv_bfloat16 t2 = __float2bfloat16_rn(r1);
      float r2 = r1 - __bfloat162float(t2);
      __nv_bfloat16 t3 = __float2bfloat16_rn(r2);
      a1[j]=t1; a2[j]=t2; a3[j]=t3;
    }
    __nv_bfloat162 p;
    p.x=a1[0]; p.y=a1[1]; o1[c4*2]=p;  p.x=a1[2]; p.y=a1[3]; o1[c4*2+1]=p;
    p.x=a2[0]; p.y=a2[1]; o2[c4*2]=p;  p.x=a2[2]; p.y=a2[3]; o2[c4*2+1]=p;
    p.x=a3[0]; p.y=a3[1]; o3[c4*2]=p;  p.x=a3[2]; p.y=a3[3]; o3[c4*2+1]=p;
  }
  g_sq[bn] = s;
}

// ---------------- knn kernel: tensor path (sm_103a) or scalar fallback ----------------
#define KN_TMEMPTR 0
#define KN_MBAR    8
#define KN_B0      1024
#define KN_TILE    49152
#define KN_B1      (KN_B0 + KN_TILE)      // 50176
#define KN_SQ      (KN_B1 + KN_TILE)      // 99328
#define KN_SMEM    (KN_SQ + 1024)         // 100352
#define KN_IDESC   0x8200490u   // f32 acc, bf16 x bf16 K-major, N=128, M=128
#define TM_A       0            // A: 96 cols (3 chunks x 32)
#define TM_D       128          // D: 128 cols
#define TM_COLS    256

#if defined(__CUDA_ARCH__) && defined(__CUDA_ARCH_FEAT_SM103_ALL)
__device__ __forceinline__ uint32_t elect_one(){
  uint32_t p;
  asm volatile("{\n\t.reg .pred p;\n\telect.sync _|p, 0xFFFFFFFF;\n\tselp.b32 %0, 1, 0, p;\n\t}" : "=r"(p));
  return p;
}
// TS-mode f16 MMA: A in TMEM, B via SMEM descriptor
__device__ __forceinline__ void mma_f16_ts(uint32_t d, uint32_t a_tmem, uint64_t bd, uint32_t idesc, uint32_t en){
  asm volatile(
    "{\n\t.reg .pred p;\n\tsetp.ne.u32 p, %4, 0;\n\t"
    "tcgen05.mma.cta_group::1.kind::f16 [%0], [%1], %2, %3, {%5,%5,%5,%5}, p;\n\t}"
    :: "r"(d), "r"(a_tmem), "l"(bd), "r"(idesc), "r"(en), "r"(0u) : "memory");
}
// non-blocking poll
__device__ __forceinline__ void mbar_wait(uint32_t mbar, uint32_t parity){
  asm volatile(
    "{\n\t.reg .pred P1;\n\t"
    "WL%=:\n\t"
    "mbarrier.test_wait.parity.acquire.cta.shared::cta.b64 P1, [%0], %1;\n\t"
    "@!P1 bra.uni WL%=;\n\t"
    "}"
    :: "r"(mbar), "r"(parity) : "memory");
}
#define LDTM16(r, addr) \
  asm volatile("tcgen05.ld.sync.aligned.32x32b.x16.b32 " \
    "{%0,%1,%2,%3,%4,%5,%6,%7,%8,%9,%10,%11,%12,%13,%14,%15}, [%16];" \
    : "=r"((r)[0]),"=r"((r)[1]),"=r"((r)[2]),"=r"((r)[3]),"=r"((r)[4]),"=r"((r)[5]),"=r"((r)[6]),"=r"((r)[7]), \
      "=r"((r)[8]),"=r"((r)[9]),"=r"((r)[10]),"=r"((r)[11]),"=r"((r)[12]),"=r"((r)[13]),"=r"((r)[14]),"=r"((r)[15]) \
    : "r"(addr))
#define STTM32(addr, r) \
  asm volatile("tcgen05.st.sync.aligned.32x32b.x32.b32 [%0], " \
    "{%1,%2,%3,%4,%5,%6,%7,%8,%9,%10,%11,%12,%13,%14,%15,%16," \
    "%17,%18,%19,%20,%21,%22,%23,%24,%25,%26,%27,%28,%29,%30,%31,%32};" \
    :: "r"(addr), \
       "r"((r)[0]),"r"((r)[1]),"r"((r)[2]),"r"((r)[3]),"r"((r)[4]),"r"((r)[5]),"r"((r)[6]),"r"((r)[7]), \
       "r"((r)[8]),"r"((r)[9]),"r"((r)[10]),"r"((r)[11]),"r"((r)[12]),"r"((r)[13]),"r"((r)[14]),"r"((r)[15]), \
       "r"((r)[16]),"r"((r)[17]),"r"((r)[18]),"r"((r)[19]),"r"((r)[20]),"r"((r)[21]),"r"((r)[22]),"r"((r)[23]), \
       "r"((r)[24]),"r"((r)[25]),"r"((r)[26]),"r"((r)[27]),"r"((r)[28]),"r"((r)[29]),"r"((r)[30]),"r"((r)[31]) \
    : "memory")
#define TC_WAIT_LD()  asm volatile("tcgen05.wait::ld.sync.aligned;" ::: "memory")
#define TC_WAIT_ST()  asm volatile("tcgen05.wait::st.sync.aligned;" ::: "memory")
#define TC_FENCE_BEFORE() asm volatile("tcgen05.fence::before_thread_sync;" ::: "memory")
#define TC_FENCE_AFTER()  asm volatile("tcgen05.fence::after_thread_sync;" ::: "memory")
#define FENCE_ASYNC() asm volatile("fence.proxy.async.shared::cta;" ::: "memory")
#define CP_COMMIT() asm volatile("cp.async.commit_group;" ::: "memory")
#define CP_WAIT0()  asm volatile("cp.async.wait_group 0;" ::: "memory")

static constexpr uint64_t DESC_BASE_SW128 =
    (uint64_t(2)  << 61) | (uint64_t(1) << 46) | (uint64_t(64) << 32) | (uint64_t(1) << 16);
__device__ __forceinline__ uint64_t make_desc(uint32_t addr){
  return DESC_BASE_SW128 | ((uint64_t)(addr >> 4) & 0x3FFF);
}

__device__ __forceinline__ void load_tile_cp(uint32_t sb_dst, const uint4* p0, const uint4* p1, const uint4* p2, int t){
  #pragma unroll
  for(int i=0;i<12;i++){
    int chunk = i >> 2;
    int rem = ((i&3)<<8) + t;
    int row = rem >> 3;
    int col = rem & 7;
    const uint4* src = (chunk==0? p0 : (chunk==1? p1 : p2)) + row*8 + col;
    uint32_t boff = (uint32_t)((row<<7) + (col<<4));
    uint32_t dst = sb_dst + chunk*16384 + (boff ^ ((boff>>3)&0x70));
    asm volatile("cp.async.cg.shared.global [%0], [%1], 16;" :: "r"(dst), "l"(src) : "memory");
  }
}

#define INSERT(vv, ii) do{ \
  if((vv) < worst){ \
    bool done=false; \
    _Pragma("unroll") \
    for(int _s=0;_s<KNBR;_s++){ \
      if(!done && kd[_s]==worst){ kd[_s]=(vv); ki[_s]=(ii); done=true; } \
    } \
    worst = kd[0]; \
    _Pragma("unroll") \
    for(int _s=1;_s<KNBR;_s++) worst = fmaxf(worst, kd[_s]); \
  } \
}while(0)

#define SEL16(dr, jb, gcol) do{ \
  float vv[16]; \
  _Pragma("unroll") \
  for(int _j=0;_j<16;_j++) \
    vv[_j] = fmaf(-2.f, __uint_as_float((dr)[_j]), __shfl_sync(FULLMASK, sqcv, (jb)+_j)); \
  float _mn = vv[0]; \
  _Pragma("unroll") \
  for(int _j=1;_j<16;_j++) _mn = fminf(_mn, vv[_j]); \
  if(__any_sync(FULLMASK, _mn < worst)){ \
    _Pragma("unroll") \
    for(int _j=0;_j<16;_j++) INSERT(vv[_j], (gcol)+(jb)+_j); \
  } \
}while(0)
#endif // feature guard

// scalar fallback worker: one 64-row R2-style pass
__device__ void knn_scalar_pass(char* smemc, int b, int rbase){
  float (*sA)[68] = reinterpret_cast<float(*)[68]>(smemc);
  float (*sB)[68] = reinterpret_cast<float(*)[68]>(smemc + 17408);
  float* sqr = reinterpret_cast<float*>(smemc + 34816);
  float* sqc = reinterpret_cast<float*>(smemc + 34816 + 256);
  float* sD = &sB[0][0];
  int t = threadIdx.x;
  int lane = t & 31, warp = t >> 5;
  const float INF = __int_as_float(0x7f800000);

  __syncthreads();
  {
    int r = t>>2, cq = (t&3)*4;
    const float4* fr = reinterpret_cast<const float4*>(g_f) + (b*NP + rbase + r)*16;
    #pragma unroll
    for(int j=0;j<4;j++){
      float4 v = fr[cq+j];
      int c = (cq+j)*4;
      sA[c+0][r]=v.x; sA[c+1][r]=v.y; sA[c+2][r]=v.z; sA[c+3][r]=v.w;
    }
    if(t < 64) sqr[t] = g_sq[b*NP + rbase + t];
  }

  float kd[8]; int ki[8]; float worst[8];
  #pragma unroll
  for(int j=0;j<8;j++){ kd[j]=INF; ki[j]=0; worst[j]=INF; }

  int ty = t>>4, tx = t&15;
  for(int ct=0; ct<NP/64; ct++){
    __syncthreads();
    {
      int r = t>>2, cq = (t&3)*4;
      const float4* fr = reinterpret_cast<const float4*>(g_f) + (b*NP + ct*64 + r)*16;
      #pragma unroll
      for(int j=0;j<4;j++){
        float4 v = fr[cq+j];
        int c = (cq+j)*4;
        sB[c+0][r]=v.x; sB[c+1][r]=v.y; sB[c+2][r]=v.z; sB[c+3][r]=v.w;
      }
      if(t < 64) sqc[t] = g_sq[b*NP + ct*64 + t];
    }
    __syncthreads();
    float acc[4][4];
    #pragma unroll
    for(int i=0;i<4;i++)
      #pragma unroll
      for(int j=0;j<4;j++) acc[i][j]=0.f;
    #pragma unroll 4
    for(int c=0;c<64;c++){
      float4 a = *reinterpret_cast<const float4*>(&sA[c][ty*4]);
      float4 w = *reinterpret_cast<const float4*>(&sB[c][tx*4]);
      acc[0][0]+=a.x*w.x; acc[0][1]+=a.x*w.y; acc[0][2]+=a.x*w.z; acc[0][3]+=a.x*w.w;
      acc[1][0]+=a.y*w.x; acc[1][1]+=a.y*w.y; acc[1][2]+=a.y*w.z; acc[1][3]+=a.y*w.w;
      acc[2][0]+=a.z*w.x; acc[2][1]+=a.z*w.y; acc[2][2]+=a.z*w.z; acc[2][3]+=a.z*w.w;
      acc[3][0]+=a.w*w.x; acc[3][1]+=a.w*w.y; acc[3][2]+=a.w*w.z; acc[3][3]+=a.w*w.w;
    }
    __syncthreads();
    #pragma unroll
    for(int i=0;i<4;i++){
      int r = ty*4 + i;
      float4 d;
      d.x = sqr[r] + sqc[tx*4+0] - 2.f*acc[i][0];
      d.y = sqr[r] + sqc[tx*4+1] - 2.f*acc[i][1];
      d.z = sqr[r] + sqc[tx*4+2] - 2.f*acc[i][2];
      d.w = sqr[r] + sqc[tx*4+3] - 2.f*acc[i][3];
      *reinterpret_cast<float4*>(&sD[r*68 + tx*4]) = d;
    }
    __syncthreads();

    int base = ct*64;
    #pragma unroll
    for(int j=0;j<8;j++){
      int r = warp*8 + j;
      float d0 = sD[r*68 + lane];
      float d1 = sD[r*68 + 32 + lane];
      float w = worst[j];
      unsigned m0 = __ballot_sync(FULLMASK, d0 < w);
      unsigned m1 = __ballot_sync(FULLMASK, d1 < w);
      while(m0 | m1){
        float cd; int cm;
        if(m0){ int src=__ffs(m0)-1; m0 &= m0-1; cd=__shfl_sync(FULLMASK,d0,src); cm=base+src; }
        else  { int src=__ffs(m1)-1; m1 &= m1-1; cd=__shfl_sync(FULLMASK,d1,src); cm=base+32+src; }
        float bv = (lane < KNBR) ? kd[j] : -INF;
        int bl = lane;
        #pragma unroll
        for(int off=16; off; off>>=1){
          float ov = __shfl_xor_sync(FULLMASK, bv, off);
          int   ol = __shfl_xor_sync(FULLMASK, bl, off);
          if(ov > bv || (ov == bv && ol < bl)){ bv = ov; bl = ol; }
        }
        if(cd < bv && lane == bl){ kd[j] = cd; ki[j] = cm; }
      }
      float bv = (lane < KNBR) ? kd[j] : -INF;
      #pragma unroll
      for(int off=16; off; off>>=1) bv = fmaxf(bv, __shfl_xor_sync(FULLMASK, bv, off));
      worst[j] = bv;
    }
  }
  #pragma unroll
  for(int j=0;j<8;j++){
    int r = warp*8 + j;
    if(lane < KNBR) g_idx[(b*NP + rbase + r)*KNBR + lane] = ki[j];
  }
}

// SINGLE CHANGE vs R9: __cluster_dims__(1,1,1). Every working tcgen05 MMA
// example carries this attribute even on 1-CTA reproducers — hypothesis:
// tcgen05.commit's shared::cluster async-proxy arrival resolves via a slow
// path on non-cluster launches (~350us/commit, matching R6-R9 measurements).
__global__ __launch_bounds__(256, 2) __cluster_dims__(1, 1, 1) void k_knn_tc(){
  extern __shared__ char smem[];
  int t = threadIdx.x;
  int b = blockIdx.y;
  int rbase = blockIdx.x*128;

#if defined(__CUDA_ARCH__) && defined(__CUDA_ARCH_FEAT_SM103_ALL)
  uint32_t sb = smem_u32(smem);
  int lane = t & 31, wid = t >> 5;

  if(wid == 0){
    asm volatile("tcgen05.alloc.cta_group::1.sync.aligned.shared::cta.b32 [%0], %1;"
                 :: "r"(sb + KN_TMEMPTR), "r"((uint32_t)TM_COLS) : "memory");
    asm volatile("tcgen05.relinquish_alloc_permit.cta_group::1.sync.aligned;");
  }
  if(t == 0){
    asm volatile("mbarrier.init.shared.b64 [%0], %1;" :: "r"(sb+KN_MBAR), "r"(1u) : "memory");
  }
  __syncthreads();
  uint32_t tbase;
  asm volatile("ld.shared.b32 %0, [%1];" : "=r"(tbase) : "r"(sb + KN_TMEMPTR));

  const uint4* P1 = reinterpret_cast<const uint4*>(g_h1);
  const uint4* P2 = reinterpret_cast<const uint4*>(g_h2);
  const uint4* P3 = reinterpret_cast<const uint4*>(g_h3);
  float* sqcb = reinterpret_cast<float*>(smem + KN_SQ);

  // ---- A -> TMEM (warps 0-3; thread t<128 owns A-row t) ----
  if(t < 128){
    uint32_t warp_off = ((uint32_t)(t>>5)) << 21;
    long rowbase = (long)(b*NP + rbase + t)*8;
    #pragma unroll
    for(int chunk=0; chunk<3; chunk++){
      const uint4* src = (chunk==0? P1 : (chunk==1? P2 : P3)) + rowbase;
      uint32_t a[32];
      #pragma unroll
      for(int q=0;q<8;q++){
        uint4 v = src[q];
        a[q*4+0]=v.x; a[q*4+1]=v.y; a[q*4+2]=v.z; a[q*4+3]=v.w;
      }
      STTM32(tbase + TM_A + chunk*32 + warp_off, a);
    }
    TC_WAIT_ST();
  }
  TC_FENCE_BEFORE();

  // ---- prologue: load B tile 0 ----
  {
    long roff = (long)(b*NP)*8;
    load_tile_cp(sb + KN_B0, P1 + roff, P2 + roff, P3 + roff, t);
    if(t < 128) sqcb[t] = g_sq[b*NP + t];
  }
  CP_COMMIT();
  __syncthreads();

  // top-k state
  float kd[KNBR]; int ki[KNBR]; float worst;
  const float INF = __int_as_float(0x7f800000);
  #pragma unroll
  for(int s=0;s<KNBR;s++){ kd[s]=INF; ki[s]=0; }
  worst = INF;

  const int pa[6] = {0,0,1,1,0,2};
  const int pb[6] = {0,1,0,1,2,0};
  int half = wid >> 2;

  for(int ct=0; ct<NP/128; ct++){
    int buf = ct & 1;
    CP_WAIT0(); FENCE_ASYNC();
    __syncthreads();

    // issue TS MMA batch -> D, commit
    if(wid == 0){
      TC_FENCE_AFTER();
      if(elect_one()){
        uint64_t bdesc = make_desc(sb + (buf ? KN_B1 : KN_B0));
        int first = 1;
        #pragma unroll
        for(int pr=0; pr<6; pr++){
          #pragma unroll
          for(int sub=0; sub<4; sub++){
            mma_f16_ts(tbase + TM_D,
                       tbase + TM_A + (uint32_t)(pa[pr]*32 + sub*8),
                       bdesc + (uint64_t)(pb[pr]*1024 + sub*2),
                       KN_IDESC, first ? 0u : 1u);
            first = 0;
          }
        }
        asm volatile("tcgen05.commit.cta_group::1.mbarrier::arrive::one.shared::cluster.b64 [%0];"
                     :: "r"(sb+KN_MBAR) : "memory");
      }
    }

    // overlap: prefetch B for tile ct+1 into the other buffer
    if(ct + 1 < NP/128){
      long roff = (long)(b*NP + (ct+1)*128)*8;
      load_tile_cp(sb + (buf ? KN_B0 : KN_B1), P1 + roff, P2 + roff, P3 + roff, t);
      if(t < 128) sqcb[(buf^1)*128 + t] = g_sq[b*NP + (ct+1)*128 + t];
    }
    CP_COMMIT();

    // wait for MMA completion (phase ct)
    mbar_wait(sb + KN_MBAR, (uint32_t)(ct & 1));
    TC_FENCE_AFTER();

    // selection from D
    {
      int gbase = ct*128;
      #pragma unroll
      for(int h=0; h<2; h++){
        int chunk = half + h*2;
        float sqcv = sqcb[buf*128 + chunk*32 + lane];
        int gcol = gbase + chunk*32;
        uint32_t dr[16];
        LDTM16(dr, tbase + TM_D + chunk*32);
        TC_WAIT_LD();
        SEL16(dr, 0, gcol);
        LDTM16(dr, tbase + TM_D + chunk*32 + 16);
        TC_WAIT_LD();
        SEL16(dr, 16, gcol);
      }
      TC_FENCE_BEFORE();
    }
  }
  __syncthreads();

  // merge halves (reuse B0 region)
  float* mv = reinterpret_cast<float*>(smem + KN_B0);
  int*   mi = reinterpret_cast<int*>(smem + KN_B0 + 128*40*4);
  {
    int rloc = ((wid&3)<<5) + lane;
    int off = rloc*40 + half*20;
    #pragma unroll
    for(int s=0;s<KNBR;s++){ mv[off+s]=kd[s]; mi[off+s]=ki[s]; }
  }
  __syncthreads();
  if(t < 128){
    float* pv = mv + t*40;
    int*   pi = mi + t*40;
    int obase = (b*NP + rbase + t)*KNBR;
    for(int k=0;k<KNBR;k++){
      float best = pv[0]; int bj = 0;
      #pragma unroll 8
      for(int j=1;j<40;j++){ float u = pv[j]; if(u < best){ best = u; bj = j; } }
      g_idx[obase + k] = pi[bj];
      pv[bj] = INF;
    }
  }
  __syncthreads();
  if(t == 0){
    asm volatile("mbarrier.inval.shared.b64 [%0];" :: "r"(sb+KN_MBAR) : "memory");
  }
  __syncthreads();
  if(wid == 0){
    asm volatile("tcgen05.dealloc.cta_group::1.sync.aligned.b32 %0, %1;"
                 :: "r"(tbase), "r"((uint32_t)TM_COLS));
  }
#else
  // scalar fallback: two 64-row passes (non-a target)
  knn_scalar_pass(smem, b, rbase);
  knn_scalar_pass(smem, b, rbase + 64);
  (void)t;
#endif
}

// ---------------- P/Q gemms ----------------
__global__ __launch_bounds__(256) void k_gemm64(int which){
  __shared__ float sA[64][68];
  __shared__ float sW[64][68];
  const float* __restrict__ Wm = which ? g_W1d : g_W1a;
  float* __restrict__ Out = which ? g_Q : g_P;
  int t = threadIdx.x;
  int b = blockIdx.y; int rbase = blockIdx.x*64;
  {
    int r = t>>2, cq = (t&3)*4;
    const float4* fr = reinterpret_cast<const float4*>(g_f) + (b*NP + rbase + r)*16;
    #pragma unroll
    for(int j=0;j<4;j++){
      float4 v = fr[cq+j];
      int c = (cq+j)*4;
      sA[c+0][r]=v.x; sA[c+1][r]=v.y; sA[c+2][r]=v.z; sA[c+3][r]=v.w;
    }
  }
  for(int i=t;i<4096;i+=256){ int o=i>>6, c=i&63; sW[c][o] = Wm[o*64+c]; }
  __syncthreads();
  int ty=t>>4, tx=t&15;
  float acc[4][4];
  #pragma unroll
  for(int i=0;i<4;i++)
    #pragma unroll
    for(int j=0;j<4;j++) acc[i][j]=0.f;
  #pragma unroll 4
  for(int c=0;c<64;c++){
    float4 a = *reinterpret_cast<const float4*>(&sA[c][ty*4]);
    float4 w = *reinterpret_cast<const float4*>(&sW[c][tx*4]);
    acc[0][0]+=a.x*w.x; acc[0][1]+=a.x*w.y; acc[0][2]+=a.x*w.z; acc[0][3]+=a.x*w.w;
    acc[1][0]+=a.y*w.x; acc[1][1]+=a.y*w.y; acc[1][2]+=a.y*w.z; acc[1][3]+=a.y*w.w;
    acc[2][0]+=a.z*w.x; acc[2][1]+=a.z*w.y; acc[2][2]+=a.z*w.z; acc[2][3]+=a.z*w.w;
    acc[3][0]+=a.w*w.x; acc[3][1]+=a.w*w.y; acc[3][2]+=a.w*w.z; acc[3][3]+=a.w*w.w;
  }
  float4* O4 = reinterpret_cast<float4*>(Out) + (b*NP + rbase)*16;
  #pragma unroll
  for(int i=0;i<4;i++)
    O4[(ty*4+i)*16 + tx] = make_float4(acc[i][0],acc[i][1],acc[i][2],acc[i][3]);
}

// ---------------- BN1 stats ----------------
__global__ __launch_bounds__(256) void k_stats1(){
  __shared__ float r1[4][64];
  __shared__ float r2[4][64];
  int t = threadIdx.x;
  int o = t & 63, sub = t >> 6;
  int base = blockIdx.x * 512;
  float s1 = 0.f, s2 = 0.f;
  for(int i = sub; i < 512; i += 4){
    int s = base + i;
    int bn = s / KNBR;
    int b = bn >> 13;
    int m = g_idx[s];
    float h = g_P[((b<<13)+m)*64 + o] + g_Q[bn*64 + o];
    s1 += h; s2 += h*h;
  }
  r1[sub][o] = s1; r2[sub][o] = s2;
  __syncthreads();
  if(sub == 0){
    atomicAdd(&g_stats1[o],    r1[0][o]+r1[1][o]+r1[2][o]+r1[3][o]);
    atomicAdd(&g_stats1[64+o], r2[0][o]+r2[1][o]+r2[2][o]+r2[3][o]);
  }
}

// ---------------- BN finalize ----------------
__global__ void k_bnfin(const float* __restrict__ g, const float* __restrict__ bb, int which){
  int o = threadIdx.x;
  const float* stats = which ? g_stats2 : g_stats1;
  const float inv = 1.f/(float)NSAMP;
  float mu  = stats[o]*inv;
  float var = stats[64+o]*inv - mu*mu;
  float rstd = rsqrtf(var + 1e-5f);
  float sc = g[o]*rstd;
  if(which){ g_scale2[o]=sc; g_shift2[o]=bb[o]-mu*sc; }
  else     { g_scale1[o]=sc; g_shift1[o]=bb[o]-mu*sc; }
}

// ---------------- conv2 + BN2 stats + max/min over k ----------------
#define PTS_PER 16
__global__ __launch_bounds__(256) void k_conv2(const float* __restrict__ W2){
  __shared__ float sA[64][68];
  __shared__ float sW[64][68];
  __shared__ float sScale[64], sShift[64];
  __shared__ float r1[4][64];
  __shared__ float r2[4][64];
  int t = threadIdx.x;
  const float INF = __int_as_float(0x7f800000);

  for(int i=t;i<4096;i+=256){ int o=i>>6, c=i&63; sW[c][o] = W2[o*64+c]; }
  if(t < 64){ sScale[t]=g_scale1[t]; sShift[t]=g_shift1[t]; }

  float ls1 = 0.f, ls2 = 0.f;
  float rmax[4], rmin[4];
  #pragma unroll
  for(int q=0;q<4;q++){ rmax[q]=-INF; rmin[q]=INF; }

  int ty=t>>4, tx=t&15;
  int myo = t & 63;
  int Sbase = blockIdx.x * (PTS_PER*KNBR);
  int pbase = blockIdx.x * PTS_PER;
  float* sH = &sA[0][0];

  for(int st=0; st<5; st++){
    __syncthreads();
    {
      int sl = t>>2, cq = (t&3)*4;
      int s = Sbase + st*64 + sl;
      int bn = s / KNBR;
      int b = bn >> 13;
      int m = g_idx[s];
      const float4* Pm = reinterpret_cast<const float4*>(g_P) + ((b<<13)+m)*16;
      const float4* Qn = reinterpret_cast<const float4*>(g_Q) + bn*16;
      #pragma unroll
      for(int j=0;j<4;j++){
        int cc = (cq+j)*4;
        float4 p = Pm[cq+j]; float4 q = Qn[cq+j];
        float v0=(p.x+q.x)*sScale[cc+0]+sShift[cc+0]; v0 = v0>=0.f? v0 : 0.2f*v0;
        float v1=(p.y+q.y)*sScale[cc+1]+sShift[cc+1]; v1 = v1>=0.f? v1 : 0.2f*v1;
        float v2=(p.z+q.z)*sScale[cc+2]+sShift[cc+2]; v2 = v2>=0.f? v2 : 0.2f*v2;
        float v3=(p.w+q.w)*sScale[cc+3]+sShift[cc+3]; v3 = v3>=0.f? v3 : 0.2f*v3;
        sA[cc+0][sl]=v0; sA[cc+1][sl]=v1; sA[cc+2][sl]=v2; sA[cc+3][sl]=v3;
      }
    }
    __syncthreads();

    float acc[4][4];
    #pragma unroll
    for(int i=0;i<4;i++)
      #pragma unroll
      for(int j=0;j<4;j++) acc[i][j]=0.f;
    #pragma unroll 4
    for(int c=0;c<64;c++){
      float4 a = *reinterpret_cast<const float4*>(&sA[c][ty*4]);
      float4 w = *reinterpret_cast<const float4*>(&sW[c][tx*4]);
      acc[0][0]+=a.x*w.x; acc[0][1]+=a.x*w.y; acc[0][2]+=a.x*w.z; acc[0][3]+=a.x*w.w;
      acc[1][0]+=a.y*w.x; acc[1][1]+=a.y*w.y; acc[1][2]+=a.y*w.z; acc[1][3]+=a.y*w.w;
      acc[2][0]+=a.z*w.x; acc[2][1]+=a.z*w.y; acc[2][2]+=a.z*w.z; acc[2][3]+=a.z*w.w;
      acc[3][0]+=a.w*w.x; acc[3][1]+=a.w*w.y; acc[3][2]+=a.w*w.z; acc[3][3]+=a.w*w.w;
    }
    __syncthreads();
    #pragma unroll
    for(int i=0;i<4;i++)
      #pragma unroll
      for(int j=0;j<4;j++)
        sH[(tx*4+j)*68 + ty*4+i] = acc[i][j];
    __syncthreads();
    #pragma unroll
    for(int q=0;q<4;q++){
      int p = (t>>6) + q*4;
      int s0 = p*KNBR - st*64;
      int s1e = s0 + KNBR;
      if(s0 < 0) s0 = 0;
      if(s1e > 64) s1e = 64;
      float mx = rmax[q], mn = rmin[q];
      for(int s=s0; s<s1e; s++){
        float v = sH[myo*68 + s];
        ls1 += v; ls2 += v*v;
        mx = fmaxf(mx, v); mn = fminf(mn, v);
      }
      rmax[q] = mx; rmin[q] = mn;
    }
  }

  #pragma unroll
  for(int q=0;q<4;q++){
    int p = (t>>6) + q*4;
    g_gmax[(pbase+p)*64 + myo] = rmax[q];
    g_gmin[(pbase+p)*64 + myo] = rmin[q];
  }
  r1[t>>6][myo] = ls1;
  r2[t>>6][myo] = ls2;
  __syncthreads();
  if(t < 64){
    atomicAdd(&g_stats2[t],    r1[0][t]+r1[1][t]+r1[2][t]+r1[3][t]);
    atomicAdd(&g_stats2[64+t], r2[0][t]+r2[1][t]+r2[2][t]+r2[3][t]);
  }
}

// ---------------- output ----------------
__global__ void k_out(float* __restrict__ out){
  int n = blockIdx.x*256 + threadIdx.x;
  int o = blockIdx.y, b = blockIdx.z;
  float s = g_scale2[o], tsh = g_shift2[o];
  const float* src = (s >= 0.f) ? g_gmax : g_gmin;
  float v = src[(b*NP + n)*64 + o];
  float h = s*v + tsh;
  out[(b*64 + o)*NP + n] = (h >= 0.f) ? h : 0.2f*h;
}

extern "C" void kernel_launch(void* const* d_in, const int* in_sizes, int n_in,
                              void* d_out, int out_size){
  const float* x  = (const float*)d_in[0];
  const float* W1 = (const float*)d_in[1];
  const float* g1 = (const float*)d_in[2];
  const float* b1 = (const float*)d_in[3];
  const float* W2 = (const float*)d_in[4];
  const float* g2 = (const float*)d_in[5];
  const float* b2 = (const float*)d_in[6];
  float* out = (float*)d_out;

  cudaFuncSetAttribute(k_knn_tc, cudaFuncAttributeMaxDynamicSharedMemorySize, KN_SMEM);

  k_prep<<<64, 64>>>(W1);
  k_transpose<<<dim3(NP/256, NB), 256>>>(x);
  k_gemm64<<<dim3(NP/64, NB), 256>>>(0);
  k_gemm64<<<dim3(NP/64, NB), 256>>>(1);
  k_knn_tc<<<dim3(NP/128, NB), 256, KN_SMEM>>>();
  k_stats1<<<NSAMP/512, 256>>>();
  k_bnfin<<<1, 64>>>(g1, b1, 0);
  k_conv2<<<NPT/PTS_PER, 256>>>(W2);
  k_bnfin<<<1, 64>>>(g2, b2, 1);
  k_out<<<dim3(NP/256, 64, NB), 256>>>(out);
}

// round 12
// speedup vs baseline: 1.0043x; 1.0034x over previous
#include <cuda_runtime.h>
#include <cuda_bf16.h>
#include <cstdint>
#include <stdint.h>

#define NB 4
#define NC 64
#define NP 8192
#define KNBR 20
#define NPT (NB*NP)
#define NSAMP (NPT*KNBR)
#define FULLMASK 0xffffffffu

__device__ __align__(16) float g_f[NPT*NC];
__device__ float g_sq[NPT];
__device__ int   g_idx[NSAMP];
__device__ __align__(16) float g_P[NPT*NC];
__device__ __align__(16) float g_Q[NPT*NC];
__device__ float g_W1a[64*64];
__device__ float g_W1d[64*64];
__device__ float g_stats1[128];
__device__ float g_stats2[128];
__device__ float g_scale1[64], g_shift1[64];
__device__ float g_scale2[64], g_shift2[64];
__device__ __align__(16) float g_gmax[NPT*64];
__device__ __align__(16) float g_gmin[NPT*64];
// bf16 3-term split planes, [NPT][64] each, K-major
__device__ __align__(16) __nv_bfloat16 g_h1[NPT*64];
__device__ __align__(16) __nv_bfloat16 g_h2[NPT*64];
__device__ __align__(16) __nv_bfloat16 g_h3[NPT*64];

// ---------------- helpers (arch-neutral) ----------------
__device__ __forceinline__ uint32_t smem_u32(const void* p){
  uint32_t a;
  asm("{ .reg .u64 t; cvta.to.shared.u64 t, %1; cvt.u32.u64 %0, t; }" : "=r"(a) : "l"(p));
  return a;
}

// ---------------- prep ----------------
__global__ void k_prep(const float* __restrict__ W1){
  int o = blockIdx.x, c = threadIdx.x;
  float a  = W1[o*128 + c];
  float bb = W1[o*128 + 64 + c];
  g_W1a[o*64+c] = a;
  g_W1d[o*64+c] = bb - a;
  if(o == 0){
    g_stats1[c] = 0.f; g_stats1[64+c] = 0.f;
    g_stats2[c] = 0.f; g_stats2[64+c] = 0.f;
  }
}

// ---------------- transpose + sq + bf16 split ----------------
__global__ void k_transpose(const float* __restrict__ x){
  int b = blockIdx.y;
  int n = blockIdx.x*256 + threadIdx.x;
  const float* xb = x + b*NC*NP;
  int bn = b*NP + n;
  float4* f4 = reinterpret_cast<float4*>(g_f) + bn*16;
  __nv_bfloat162* o1 = reinterpret_cast<__nv_bfloat162*>(g_h1) + bn*32;
  __nv_bfloat162* o2 = reinterpret_cast<__nv_bfloat162*>(g_h2) + bn*32;
  __nv_bfloat162* o3 = reinterpret_cast<__nv_bfloat162*>(g_h3) + bn*32;
  float s = 0.f;
  #pragma unroll
  for(int c4=0; c4<16; c4++){
    float4 v;
    v.x = xb[(4*c4+0)*NP + n];
    v.y = xb[(4*c4+1)*NP + n];
    v.z = xb[(4*c4+2)*NP + n];
    v.w = xb[(4*c4+3)*NP + n];
    s += v.x*v.x + v.y*v.y + v.z*v.z + v.w*v.w;
    f4[c4] = v;
    float vv[4] = {v.x, v.y, v.z, v.w};
    __nv_bfloat16 a1[4], a2[4], a3[4];
    #pragma unroll
    for(int j=0;j<4;j++){
      float f = vv[j];
      __nv_bfloat16 t1 = __float2bfloat16_rn(f);
      float r1 = f - __bfloat162float(t1);
      __nv_bfloat16 t2 = __float2bfloat16_rn(r1);
      float r2 = r1 - __bfloat162float(t2);
      __nv_bfloat16 t3 = __float2bfloat16_rn(r2);
      a1[j]=t1; a2[j]=t2; a3[j]=t3;
    }
    __nv_bfloat162 p;
    p.x=a1[0]; p.y=a1[1]; o1[c4*2]=p;  p.x=a1[2]; p.y=a1[3]; o1[c4*2+1]=p;
    p.x=a2[0]; p.y=a2[1]; o2[c4*2]=p;  p.x=a2[2]; p.y=a2[3]; o2[c4*2+1]=p;
    p.x=a3[0]; p.y=a3[1]; o3[c4*2]=p;  p.x=a3[2]; p.y=a3[3]; o3[c4*2+1]=p;
  }
  g_sq[bn] = s;
}

// ---------------- knn kernel: tensor path (sm_103a) or scalar fallback ----------------
#define KN_TMEMPTR 0
#define KN_B0      1024
#define KN_TILE    49152
#define KN_B1      (KN_B0 + KN_TILE)      // 50176
#define KN_SQ      (KN_B1 + KN_TILE)      // 99328
#define KN_BD      (KN_SQ + 1024)         // 100352, 1KB dummy-B constants
#define KN_SMEM    (KN_BD + 1024)         // 101376
#define KN_IDESC   0x8200490u   // f32 acc, bf16 x bf16 K-major, N=128, M=128
#define KN_IDESC_DUMMY 0x8020490u // same, N=8
#define TM_A       0            // A: 96 cols
#define TM_FLAG0   96           // sentinel flags: 2 x 8 cols
#define TM_FLAG1   104
#define TM_D       128          // D: 128 cols
#define TM_COLS    256
#define POISON     0xFF7FFFFFu

#if defined(__CUDA_ARCH__) && defined(__CUDA_ARCH_FEAT_SM103_ALL)
__device__ __forceinline__ uint32_t elect_one(){
  uint32_t p;
  asm volatile("{\n\t.reg .pred p;\n\telect.sync _|p, 0xFFFFFFFF;\n\tselp.b32 %0, 1, 0, p;\n\t}" : "=r"(p));
  return p;
}
__device__ __forceinline__ void mma_f16_ts(uint32_t d, uint32_t a_tmem, uint64_t bd, uint32_t idesc, uint32_t en){
  asm volatile(
    "{\n\t.reg .pred p;\n\tsetp.ne.u32 p, %4, 0;\n\t"
    "tcgen05.mma.cta_group::1.kind::f16 [%0], [%1], %2, %3, {%5,%5,%5,%5}, p;\n\t}"
    :: "r"(d), "r"(a_tmem), "l"(bd), "r"(idesc), "r"(en), "r"(0u) : "memory");
}
#define LDTM16(r, addr) \
  asm volatile("tcgen05.ld.sync.aligned.32x32b.x16.b32 " \
    "{%0,%1,%2,%3,%4,%5,%6,%7,%8,%9,%10,%11,%12,%13,%14,%15}, [%16];" \
    : "=r"((r)[0]),"=r"((r)[1]),"=r"((r)[2]),"=r"((r)[3]),"=r"((r)[4]),"=r"((r)[5]),"=r"((r)[6]),"=r"((r)[7]), \
      "=r"((r)[8]),"=r"((r)[9]),"=r"((r)[10]),"=r"((r)[11]),"=r"((r)[12]),"=r"((r)[13]),"=r"((r)[14]),"=r"((r)[15]) \
    : "r"(addr))
#define LDTM1(v, addr) \
  asm volatile("tcgen05.ld.sync.aligned.32x32b.x1.b32 {%0}, [%1];" : "=r"(v) : "r"(addr))
#define STTM1(addr, v) \
  asm volatile("tcgen05.st.sync.aligned.32x32b.x1.b32 [%0], {%1};" :: "r"(addr), "r"(v) : "memory")
#define STTM32(addr, r) \
  asm volatile("tcgen05.st.sync.aligned.32x32b.x32.b32 [%0], " \
    "{%1,%2,%3,%4,%5,%6,%7,%8,%9,%10,%11,%12,%13,%14,%15,%16," \
    "%17,%18,%19,%20,%21,%22,%23,%24,%25,%26,%27,%28,%29,%30,%31,%32};" \
    :: "r"(addr), \
       "r"((r)[0]),"r"((r)[1]),"r"((r)[2]),"r"((r)[3]),"r"((r)[4]),"r"((r)[5]),"r"((r)[6]),"r"((r)[7]), \
       "r"((r)[8]),"r"((r)[9]),"r"((r)[10]),"r"((r)[11]),"r"((r)[12]),"r"((r)[13]),"r"((r)[14]),"r"((r)[15]), \
       "r"((r)[16]),"r"((r)[17]),"r"((r)[18]),"r"((r)[19]),"r"((r)[20]),"r"((r)[21]),"r"((r)[22]),"r"((r)[23]), \
       "r"((r)[24]),"r"((r)[25]),"r"((r)[26]),"r"((r)[27]),"r"((r)[28]),"r"((r)[29]),"r"((r)[30]),"r"((r)[31]) \
    : "memory")
#define TC_WAIT_LD()  asm volatile("tcgen05.wait::ld.sync.aligned;" ::: "memory")
#define TC_WAIT_ST()  asm volatile("tcgen05.wait::st.sync.aligned;" ::: "memory")
#define TC_FENCE_BEFORE() asm volatile("tcgen05.fence::before_thread_sync;" ::: "memory")
#define TC_FENCE_AFTER()  asm volatile("tcgen05.fence::after_thread_sync;" ::: "memory")
#define FENCE_ASYNC() asm volatile("fence.proxy.async.shared::cta;" ::: "memory")
#define CP_COMMIT() asm volatile("cp.async.commit_group;" ::: "memory")
#define CP_WAIT0()  asm volatile("cp.async.wait_group 0;" ::: "memory")

static constexpr uint64_t DESC_BASE_SW128 =
    (uint64_t(2)  << 61) | (uint64_t(1) << 46) | (uint64_t(64) << 32) | (uint64_t(1) << 16);
__device__ __forceinline__ uint64_t make_desc(uint32_t addr){
  return DESC_BASE_SW128 | ((uint64_t)(addr >> 4) & 0x3FFF);
}

__device__ __forceinline__ void load_tile_cp(uint32_t sb_dst, const uint4* p0, const uint4* p1, const uint4* p2, int t){
  #pragma unroll
  for(int i=0;i<12;i++){
    int chunk = i >> 2;
    int rem = ((i&3)<<8) + t;
    int row = rem >> 3;
    int col = rem & 7;
    const uint4* src = (chunk==0? p0 : (chunk==1? p1 : p2)) + row*8 + col;
    uint32_t boff = (uint32_t)((row<<7) + (col<<4));
    uint32_t dst = sb_dst + chunk*16384 + (boff ^ ((boff>>3)&0x70));
    asm volatile("cp.async.cg.shared.global [%0], [%1], 16;" :: "r"(dst), "l"(src) : "memory");
  }
}

#define INSERT(vv, ii) do{ \
  if((vv) < worst){ \
    bool done=false; \
    _Pragma("unroll") \
    for(int _s=0;_s<KNBR;_s++){ \
      if(!done && kd[_s]==worst){ kd[_s]=(vv); ki[_s]=(ii); done=true; } \
    } \
    worst = kd[0]; \
    _Pragma("unroll") \
    for(int _s=1;_s<KNBR;_s++) worst = fmaxf(worst, kd[_s]); \
  } \
}while(0)

#define SEL16(dr, jb, gcol) do{ \
  float vv[16]; \
  _Pragma("unroll") \
  for(int _j=0;_j<16;_j++) \
    vv[_j] = fmaf(-2.f, __uint_as_float((dr)[_j]), __shfl_sync(FULLMASK, sqcv, (jb)+_j)); \
  float _mn = vv[0]; \
  _Pragma("unroll") \
  for(int _j=1;_j<16;_j++) _mn = fminf(_mn, vv[_j]); \
  if(__any_sync(FULLMASK, _mn < worst)){ \
    _Pragma("unroll") \
    for(int _j=0;_j<16;_j++) INSERT(vv[_j], (gcol)+(jb)+_j); \
  } \
}while(0)
#endif // feature guard

// scalar fallback worker: one 64-row R2-style pass
__device__ void knn_scalar_pass(char* smemc, int b, int rbase){
  float (*sA)[68] = reinterpret_cast<float(*)[68]>(smemc);
  float (*sB)[68] = reinterpret_cast<float(*)[68]>(smemc + 17408);
  float* sqr = reinterpret_cast<float*>(smemc + 34816);
  float* sqc = reinterpret_cast<float*>(smemc + 34816 + 256);
  float* sD = &sB[0][0];
  int t = threadIdx.x;
  int lane = t & 31, warp = t >> 5;
  const float INF = __int_as_float(0x7f800000);

  __syncthreads();
  {
    int r = t>>2, cq = (t&3)*4;
    const float4* fr = reinterpret_cast<const float4*>(g_f) + (b*NP + rbase + r)*16;
    #pragma unroll
    for(int j=0;j<4;j++){
      float4 v = fr[cq+j];
      int c = (cq+j)*4;
      sA[c+0][r]=v.x; sA[c+1][r]=v.y; sA[c+2][r]=v.z; sA[c+3][r]=v.w;
    }
    if(t < 64) sqr[t] = g_sq[b*NP + rbase + t];
  }

  float kd[8]; int ki[8]; float worst[8];
  #pragma unroll
  for(int j=0;j<8;j++){ kd[j]=INF; ki[j]=0; worst[j]=INF; }

  int ty = t>>4, tx = t&15;
  for(int ct=0; ct<NP/64; ct++){
    __syncthreads();
    {
      int r = t>>2, cq = (t&3)*4;
      const float4* fr = reinterpret_cast<const float4*>(g_f) + (b*NP + ct*64 + r)*16;
      #pragma unroll
      for(int j=0;j<4;j++){
        float4 v = fr[cq+j];
        int c = (cq+j)*4;
        sB[c+0][r]=v.x; sB[c+1][r]=v.y; sB[c+2][r]=v.z; sB[c+3][r]=v.w;
      }
      if(t < 64) sqc[t] = g_sq[b*NP + ct*64 + t];
    }
    __syncthreads();
    float acc[4][4];
    #pragma unroll
    for(int i=0;i<4;i++)
      #pragma unroll
      for(int j=0;j<4;j++) acc[i][j]=0.f;
    #pragma unroll 4
    for(int c=0;c<64;c++){
      float4 a = *reinterpret_cast<const float4*>(&sA[c][ty*4]);
      float4 w = *reinterpret_cast<const float4*>(&sB[c][tx*4]);
      acc[0][0]+=a.x*w.x; acc[0][1]+=a.x*w.y; acc[0][2]+=a.x*w.z; acc[0][3]+=a.x*w.w;
      acc[1][0]+=a.y*w.x; acc[1][1]+=a.y*w.y; acc[1][2]+=a.y*w.z; acc[1][3]+=a.y*w.w;
      acc[2][0]+=a.z*w.x; acc[2][1]+=a.z*w.y; acc[2][2]+=a.z*w.z; acc[2][3]+=a.z*w.w;
      acc[3][0]+=a.w*w.x; acc[3][1]+=a.w*w.y; acc[3][2]+=a.w*w.z; acc[3][3]+=a.w*w.w;
    }
    __syncthreads();
    #pragma unroll
    for(int i=0;i<4;i++){
      int r = ty*4 + i;
      float4 d;
      d.x = sqr[r] + sqc[tx*4+0] - 2.f*acc[i][0];
      d.y = sqr[r] + sqc[tx*4+1] - 2.f*acc[i][1];
      d.z = sqr[r] + sqc[tx*4+2] - 2.f*acc[i][2];
      d.w = sqr[r] + sqc[tx*4+3] - 2.f*acc[i][3];
      *reinterpret_cast<float4*>(&sD[r*68 + tx*4]) = d;
    }
    __syncthreads();

    int base = ct*64;
    #pragma unroll
    for(int j=0;j<8;j++){
      int r = warp*8 + j;
      float d0 = sD[r*68 + lane];
      float d1 = sD[r*68 + 32 + lane];
      float w = worst[j];
      unsigned m0 = __ballot_sync(FULLMASK, d0 < w);
      unsigned m1 = __ballot_sync(FULLMASK, d1 < w);
      while(m0 | m1){
        float cd; int cm;
        if(m0){ int src=__ffs(m0)-1; m0 &= m0-1; cd=__shfl_sync(FULLMASK,d0,src); cm=base+src; }
        else  { int src=__ffs(m1)-1; m1 &= m1-1; cd=__shfl_sync(FULLMASK,d1,src); cm=base+32+src; }
        float bv = (lane < KNBR) ? kd[j] : -INF;
        int bl = lane;
        #pragma unroll
        for(int off=16; off; off>>=1){
          float ov = __shfl_xor_sync(FULLMASK, bv, off);
          int   ol = __shfl_xor_sync(FULLMASK, bl, off);
          if(ov > bv || (ov == bv && ol < bl)){ bv = ov; bl = ol; }
        }
        if(cd < bv && lane == bl){ kd[j] = cd; ki[j] = cm; }
      }
      float bv = (lane < KNBR) ? kd[j] : -INF;
      #pragma unroll
      for(int off=16; off; off>>=1) bv = fmaxf(bv, __shfl_xor_sync(FULLMASK, bv, off));
      worst[j] = bv;
    }
  }
  #pragma unroll
  for(int j=0;j<8;j++){
    int r = warp*8 + j;
    if(lane < KNBR) g_idx[(b*NP + rbase + r)*KNBR + lane] = ki[j];
  }
}

// Commit/mbarrier path abandoned (R6-R10: ~350us per commit->signal, invariant
// to wait mechanism / SS-TS / cluster attr). This version detects MMA batch
// completion by polling a TMEM sentinel: a dummy M=128,N=8 MMA issued AFTER the
// real batch overwrites a poisoned flag column; in-order tensor-pipe completion
// implies D is ready when the poison disappears. Wrong-order => rel_err fails.
__global__ __launch_bounds__(256, 2) void k_knn_tc(){
  extern __shared__ char smem[];
  int t = threadIdx.x;
  int b = blockIdx.y;
  int rbase = blockIdx.x*128;

#if defined(__CUDA_ARCH__) && defined(__CUDA_ARCH_FEAT_SM103_ALL)
  uint32_t sb = smem_u32(smem);
  int lane = t & 31, wid = t >> 5;

  if(wid == 0){
    asm volatile("tcgen05.alloc.cta_group::1.sync.aligned.shared::cta.b32 [%0], %1;"
                 :: "r"(sb + KN_TMEMPTR), "r"((uint32_t)TM_COLS) : "memory");
    asm volatile("tcgen05.relinquish_alloc_permit.cta_group::1.sync.aligned;");
  }
  __syncthreads();
  uint32_t tbase;
  asm volatile("ld.shared.b32 %0, [%1];" : "=r"(tbase) : "r"(sb + KN_TMEMPTR));

  const uint4* P1 = reinterpret_cast<const uint4*>(g_h1);
  const uint4* P2 = reinterpret_cast<const uint4*>(g_h2);
  const uint4* P3 = reinterpret_cast<const uint4*>(g_h3);
  float* sqcb = reinterpret_cast<float*>(smem + KN_SQ);

  // dummy-B constants: fill 1KB with bf16 1.0 pairs
  reinterpret_cast<uint32_t*>(smem + KN_BD)[t] = 0x3F803F80u;

  // A -> TMEM + poison both flag columns (warps 0-3; thread t<128 owns A-row t)
  if(t < 128){
    uint32_t warp_off = ((uint32_t)(t>>5)) << 21;
    long rowbase = (long)(b*NP + rbase + t)*8;
    #pragma unroll
    for(int chunk=0; chunk<3; chunk++){
      const uint4* src = (chunk==0? P1 : (chunk==1? P2 : P3)) + rowbase;
      uint32_t a[32];
      #pragma unroll
      for(int q=0;q<8;q++){
        uint4 v = src[q];
        a[q*4+0]=v.x; a[q*4+1]=v.y; a[q*4+2]=v.z; a[q*4+3]=v.w;
      }
      STTM32(tbase + TM_A + chunk*32 + warp_off, a);
    }
    STTM1(tbase + TM_FLAG0 + warp_off, POISON);
    STTM1(tbase + TM_FLAG1 + warp_off, POISON);
    TC_WAIT_ST();
  }
  TC_FENCE_BEFORE();

  // prologue: load B tile 0
  {
    long roff = (long)(b*NP)*8;
    load_tile_cp(sb + KN_B0, P1 + roff, P2 + roff, P3 + roff, t);
    if(t < 128) sqcb[t] = g_sq[b*NP + t];
  }
  CP_COMMIT();
  __syncthreads();

  float kd[KNBR]; int ki[KNBR]; float worst;
  const float INF = __int_as_float(0x7f800000);
  #pragma unroll
  for(int s=0;s<KNBR;s++){ kd[s]=INF; ki[s]=0; }
  worst = INF;

  const int pa[6] = {0,0,1,1,0,2};
  const int pb[6] = {0,1,0,1,2,0};
  int half = wid >> 2;
  uint64_t bddesc = make_desc(sb + KN_BD);

  for(int ct=0; ct<NP/128; ct++){
    int buf = ct & 1;
    uint32_t flag = tbase + (buf ? TM_FLAG1 : TM_FLAG0);
    CP_WAIT0(); FENCE_ASYNC();
    __syncthreads();

    // issue TS MMA batch -> D, then sentinel MMA -> flag (no commit)
    if(wid == 0){
      TC_FENCE_AFTER();
      if(elect_one()){
        uint64_t bdesc = make_desc(sb + (buf ? KN_B1 : KN_B0));
        int first = 1;
        #pragma unroll
        for(int pr=0; pr<6; pr++){
          #pragma unroll
          for(int sub=0; sub<4; sub++){
            mma_f16_ts(tbase + TM_D,
                       tbase + TM_A + (uint32_t)(pa[pr]*32 + sub*8),
                       bdesc + (uint64_t)(pb[pr]*1024 + sub*2),
                       KN_IDESC, first ? 0u : 1u);
            first = 0;
          }
        }
        mma_f16_ts(flag, tbase + TM_A, bddesc, KN_IDESC_DUMMY, 0u);
      }
    }

    // overlap: prefetch B for tile ct+1
    if(ct + 1 < NP/128){
      long roff = (long)(b*NP + (ct+1)*128)*8;
      load_tile_cp(sb + (buf ? KN_B0 : KN_B1), P1 + roff, P2 + roff, P3 + roff, t);
      if(t < 128) sqcb[(buf^1)*128 + t] = g_sq[b*NP + (ct+1)*128 + t];
    }
    CP_COMMIT();

    // poll sentinel: each warp reads its own subpartition lanes of the flag col
    {
      uint32_t v;
      do{
        LDTM1(v, flag);
        TC_WAIT_LD();
      } while(__any_sync(FULLMASK, v == POISON));
    }
    TC_FENCE_AFTER();

    // selection from D
    {
      int gbase = ct*128;
      #pragma unroll
      for(int h=0; h<2; h++){
        int chunk = half + h*2;
        float sqcv = sqcb[buf*128 + chunk*32 + lane];
        int gcol = gbase + chunk*32;
        uint32_t dr[16];
        LDTM16(dr, tbase + TM_D + chunk*32);
        TC_WAIT_LD();
        SEL16(dr, 0, gcol);
        LDTM16(dr, tbase + TM_D + chunk*32 + 16);
        TC_WAIT_LD();
        SEL16(dr, 16, gcol);
      }
    }
    // all warps (incl. the subpartition-sharing pair w/w+4) must pass the poll
    // and selection before re-poisoning this flag for tile ct+2
    __syncthreads();
    if(t < 128){
      uint32_t warp_off = ((uint32_t)(t>>5)) << 21;
      STTM1(flag + warp_off, POISON);
      TC_WAIT_ST();
    }
    TC_FENCE_BEFORE();
  }
  __syncthreads();

  // merge halves (reuse B0 region)
  float* mv = reinterpret_cast<float*>(smem + KN_B0);
  int*   mi = reinterpret_cast<int*>(smem + KN_B0 + 128*40*4);
  {
    int rloc = ((wid&3)<<5) + lane;
    int off = rloc*40 + half*20;
    #pragma unroll
    for(int s=0;s<KNBR;s++){ mv[off+s]=kd[s]; mi[off+s]=ki[s]; }
  }
  __syncthreads();
  if(t < 128){
    float* pv = mv + t*40;
    int*   pi = mi + t*40;
    int obase = (b*NP + rbase + t)*KNBR;
    for(int k=0;k<KNBR;k++){
      float best = pv[0]; int bj = 0;
      #pragma unroll 8
      for(int j=1;j<40;j++){ float u = pv[j]; if(u < best){ best = u; bj = j; } }
      g_idx[obase + k] = pi[bj];
      pv[bj] = INF;
    }
  }
  __syncthreads();
  if(wid == 0){
    asm volatile("tcgen05.dealloc.cta_group::1.sync.aligned.b32 %0, %1;"
                 :: "r"(tbase), "r"((uint32_t)TM_COLS));
  }
#else
  // scalar fallback: two 64-row passes (non-a target)
  knn_scalar_pass(smem, b, rbase);
  knn_scalar_pass(smem, b, rbase + 64);
  (void)t;
#endif
}

// ---------------- P/Q gemms ----------------
__global__ __launch_bounds__(256) void k_gemm64(int which){
  __shared__ float sA[64][68];
  __shared__ float sW[64][68];
  const float* __restrict__ Wm = which ? g_W1d : g_W1a;
  float* __restrict__ Out = which ? g_Q : g_P;
  int t = threadIdx.x;
  int b = blockIdx.y; int rbase = blockIdx.x*64;
  {
    int r = t>>2, cq = (t&3)*4;
    const float4* fr = reinterpret_cast<const float4*>(g_f) + (b*NP + rbase + r)*16;
    #pragma unroll
    for(int j=0;j<4;j++){
      float4 v = fr[cq+j];
      int c = (cq+j)*4;
      sA[c+0][r]=v.x; sA[c+1][r]=v.y; sA[c+2][r]=v.z; sA[c+3][r]=v.w;
    }
  }
  for(int i=t;i<4096;i+=256){ int o=i>>6, c=i&63; sW[c][o] = Wm[o*64+c]; }
  __syncthreads();
  int ty=t>>4, tx=t&15;
  float acc[4][4];
  #pragma unroll
  for(int i=0;i<4;i++)
    #pragma unroll
    for(int j=0;j<4;j++) acc[i][j]=0.f;
  #pragma unroll 4
  for(int c=0;c<64;c++){
    float4 a = *reinterpret_cast<const float4*>(&sA[c][ty*4]);
    float4 w = *reinterpret_cast<const float4*>(&sW[c][tx*4]);
    acc[0][0]+=a.x*w.x; acc[0][1]+=a.x*w.y; acc[0][2]+=a.x*w.z; acc[0][3]+=a.x*w.w;
    acc[1][0]+=a.y*w.x; acc[1][1]+=a.y*w.y; acc[1][2]+=a.y*w.z; acc[1][3]+=a.y*w.w;
    acc[2][0]+=a.z*w.x; acc[2][1]+=a.z*w.y; acc[2][2]+=a.z*w.z; acc[2][3]+=a.z*w.w;
    acc[3][0]+=a.w*w.x; acc[3][1]+=a.w*w.y; acc[3][2]+=a.w*w.z; acc[3][3]+=a.w*w.w;
  }
  float4* O4 = reinterpret_cast<float4*>(Out) + (b*NP + rbase)*16;
  #pragma unroll
  for(int i=0;i<4;i++)
    O4[(ty*4+i)*16 + tx] = make_float4(acc[i][0],acc[i][1],acc[i][2],acc[i][3]);
}

// ---------------- BN1 stats ----------------
__global__ __launch_bounds__(256) void k_stats1(){
  __shared__ float r1[4][64];
  __shared__ float r2[4][64];
  int t = threadIdx.x;
  int o = t & 63, sub = t >> 6;
  int base = blockIdx.x * 512;
  float s1 = 0.f, s2 = 0.f;
  for(int i = sub; i < 512; i += 4){
    int s = base + i;
    int bn = s / KNBR;
    int b = bn >> 13;
    int m = g_idx[s];
    float h = g_P[((b<<13)+m)*64 + o] + g_Q[bn*64 + o];
    s1 += h; s2 += h*h;
  }
  r1[sub][o] = s1; r2[sub][o] = s2;
  __syncthreads();
  if(sub == 0){
    atomicAdd(&g_stats1[o],    r1[0][o]+r1[1][o]+r1[2][o]+r1[3][o]);
    atomicAdd(&g_stats1[64+o], r2[0][o]+r2[1][o]+r2[2][o]+r2[3][o]);
  }
}

// ---------------- BN finalize ----------------
__global__ void k_bnfin(const float* __restrict__ g, const float* __restrict__ bb, int which){
  int o = threadIdx.x;
  const float* stats = which ? g_stats2 : g_stats1;
  const float inv = 1.f/(float)NSAMP;
  float mu  = stats[o]*inv;
  float var = stats[64+o]*inv - mu*mu;
  float rstd = rsqrtf(var + 1e-5f);
  float sc = g[o]*rstd;
  if(which){ g_scale2[o]=sc; g_shift2[o]=bb[o]-mu*sc; }
  else     { g_scale1[o]=sc; g_shift1[o]=bb[o]-mu*sc; }
}

// ---------------- conv2 + BN2 stats + max/min over k ----------------
#define PTS_PER 16
__global__ __launch_bounds__(256) void k_conv2(const float* __restrict__ W2){
  __shared__ float sA[64][68];
  __shared__ float sW[64][68];
  __shared__ float sScale[64], sShift[64];
  __shared__ float r1[4][64];
  __shared__ float r2[4][64];
  int t = threadIdx.x;
  const float INF = __int_as_float(0x7f800000);

  for(int i=t;i<4096;i+=256){ int o=i>>6, c=i&63; sW[c][o] = W2[o*64+c]; }
  if(t < 64){ sScale[t]=g_scale1[t]; sShift[t]=g_shift1[t]; }

  float ls1 = 0.f, ls2 = 0.f;
  float rmax[4], rmin[4];
  #pragma unroll
  for(int q=0;q<4;q++){ rmax[q]=-INF; rmin[q]=INF; }

  int ty=t>>4, tx=t&15;
  int myo = t & 63;
  int Sbase = blockIdx.x * (PTS_PER*KNBR);
  int pbase = blockIdx.x * PTS_PER;
  float* sH = &sA[0][0];

  for(int st=0; st<5; st++){
    __syncthreads();
    {
      int sl = t>>2, cq = (t&3)*4;
      int s = Sbase + st*64 + sl;
      int bn = s / KNBR;
      int b = bn >> 13;
      int m = g_idx[s];
      const float4* Pm = reinterpret_cast<const float4*>(g_P) + ((b<<13)+m)*16;
      const float4* Qn = reinterpret_cast<const float4*>(g_Q) + bn*16;
      #pragma unroll
      for(int j=0;j<4;j++){
        int cc = (cq+j)*4;
        float4 p = Pm[cq+j]; float4 q = Qn[cq+j];
        float v0=(p.x+q.x)*sScale[cc+0]+sShift[cc+0]; v0 = v0>=0.f? v0 : 0.2f*v0;
        float v1=(p.y+q.y)*sScale[cc+1]+sShift[cc+1]; v1 = v1>=0.f? v1 : 0.2f*v1;
        float v2=(p.z+q.z)*sScale[cc+2]+sShift[cc+2]; v2 = v2>=0.f? v2 : 0.2f*v2;
        float v3=(p.w+q.w)*sScale[cc+3]+sShift[cc+3]; v3 = v3>=0.f? v3 : 0.2f*v3;
        sA[cc+0][sl]=v0; sA[cc+1][sl]=v1; sA[cc+2][sl]=v2; sA[cc+3][sl]=v3;
      }
    }
    __syncthreads();

    float acc[4][4];
    #pragma unroll
    for(int i=0;i<4;i++)
      #pragma unroll
      for(int j=0;j<4;j++) acc[i][j]=0.f;
    #pragma unroll 4
    for(int c=0;c<64;c++){
      float4 a = *reinterpret_cast<const float4*>(&sA[c][ty*4]);
      float4 w = *reinterpret_cast<const float4*>(&sW[c][tx*4]);
      acc[0][0]+=a.x*w.x; acc[0][1]+=a.x*w.y; acc[0][2]+=a.x*w.z; acc[0][3]+=a.x*w.w;
      acc[1][0]+=a.y*w.x; acc[1][1]+=a.y*w.y; acc[1][2]+=a.y*w.z; acc[1][3]+=a.y*w.w;
      acc[2][0]+=a.z*w.x; acc[2][1]+=a.z*w.y; acc[2][2]+=a.z*w.z; acc[2][3]+=a.z*w.w;
      acc[3][0]+=a.w*w.x; acc[3][1]+=a.w*w.y; acc[3][2]+=a.w*w.z; acc[3][3]+=a.w*w.w;
    }
    __syncthreads();
    #pragma unroll
    for(int i=0;i<4;i++)
      #pragma unroll
      for(int j=0;j<4;j++)
        sH[(tx*4+j)*68 + ty*4+i] = acc[i][j];
    __syncthreads();
    #pragma unroll
    for(int q=0;q<4;q++){
      int p = (t>>6) + q*4;
      int s0 = p*KNBR - st*64;
      int s1e = s0 + KNBR;
      if(s0 < 0) s0 = 0;
      if(s1e > 64) s1e = 64;
      float mx = rmax[q], mn = rmin[q];
      for(int s=s0; s<s1e; s++){
        float v = sH[myo*68 + s];
        ls1 += v; ls2 += v*v;
        mx = fmaxf(mx, v); mn = fminf(mn, v);
      }
      rmax[q] = mx; rmin[q] = mn;
    }
  }

  #pragma unroll
  for(int q=0;q<4;q++){
    int p = (t>>6) + q*4;
    g_gmax[(pbase+p)*64 + myo] = rmax[q];
    g_gmin[(pbase+p)*64 + myo] = rmin[q];
  }
  r1[t>>6][myo] = ls1;
  r2[t>>6][myo] = ls2;
  __syncthreads();
  if(t < 64){
    atomicAdd(&g_stats2[t],    r1[0][t]+r1[1][t]+r1[2][t]+r1[3][t]);
    atomicAdd(&g_stats2[64+t], r2[0][t]+r2[1][t]+r2[2][t]+r2[3][t]);
  }
}

// ---------------- output ----------------
__global__ void k_out(float* __restrict__ out){
  int n = blockIdx.x*256 + threadIdx.x;
  int o = blockIdx.y, b = blockIdx.z;
  float s = g_scale2[o], tsh = g_shift2[o];
  const float* src = (s >= 0.f) ? g_gmax : g_gmin;
  float v = src[(b*NP + n)*64 + o];
  float h = s*v + tsh;
  out[(b*64 + o)*NP + n] = (h >= 0.f) ? h : 0.2f*h;
}

extern "C" void kernel_launch(void* const* d_in, const int* in_sizes, int n_in,
                              void* d_out, int out_size){
  const float* x  = (const float*)d_in[0];
  const float* W1 = (const float*)d_in[1];
  const float* g1 = (const float*)d_in[2];
  const float* b1 = (const float*)d_in[3];
  const float* W2 = (const float*)d_in[4];
  const float* g2 = (const float*)d_in[5];
  const float* b2 = (const float*)d_in[6];
  float* out = (float*)d_out;

  cudaFuncSetAttribute(k_knn_tc, cudaFuncAttributeMaxDynamicSharedMemorySize, KN_SMEM);

  k_prep<<<64, 64>>>(W1);
  k_transpose<<<dim3(NP/256, NB), 256>>>(x);
  k_gemm64<<<dim3(NP/64, NB), 256>>>(0);
  k_knn_tc<<<dim3(NP/128, NB), 256, KN_SMEM>>>();
  k_gemm64<<<dim3(NP/64, NB), 256>>>(1);
  k_stats1<<<NSAMP/512, 256>>>();
  k_bnfin<<<1, 64>>>(g1, b1, 0);
  k_conv2<<<NPT/PTS_PER, 256>>>(W2);
  k_bnfin<<<1, 64>>>(g2, b2, 1);
  k_out<<<dim3(NP/256, 64, NB), 256>>>(out);
}

// round 13
// speedup vs baseline: 25.2760x; 25.1678x over previous
#include <cuda_runtime.h>
#include <cuda_bf16.h>
#include <cstdint>
#include <stdint.h>

#define NB 4
#define NC 64
#define NP 8192
#define KNBR 20
#define NPT (NB*NP)
#define NSAMP (NPT*KNBR)
#define FULLMASK 0xffffffffu

__device__ __align__(16) float g_f[NPT*NC];
__device__ float g_sq[NPT];
__device__ int   g_idx[NSAMP];
__device__ __align__(16) float g_P[NPT*NC];
__device__ __align__(16) float g_Q[NPT*NC];
__device__ float g_W1a[64*64];
__device__ float g_W1d[64*64];
__device__ float g_stats1[128];
__device__ float g_stats2[128];
__device__ float g_scale1[64], g_shift1[64];
__device__ float g_scale2[64], g_shift2[64];
__device__ __align__(16) float g_gmax[NPT*64];
__device__ __align__(16) float g_gmin[NPT*64];

// ---------------- prep: W1 split + zero stats ----------------
__global__ void k_prep(const float* __restrict__ W1){
  int o = blockIdx.x, c = threadIdx.x;
  float a  = W1[o*128 + c];
  float bb = W1[o*128 + 64 + c];
  g_W1a[o*64+c] = a;
  g_W1d[o*64+c] = bb - a;
  if(o == 0){
    g_stats1[c] = 0.f; g_stats1[64+c] = 0.f;
    g_stats2[c] = 0.f; g_stats2[64+c] = 0.f;
  }
}

// ---------------- transpose x(B,C,N)->f(B,N,C) + sq norms ----------------
__global__ void k_transpose(const float* __restrict__ x){
  int b = blockIdx.y;
  int n = blockIdx.x*256 + threadIdx.x;
  const float* xb = x + b*NC*NP;
  float4* f4 = reinterpret_cast<float4*>(g_f) + (b*NP + n)*16;
  float s = 0.f;
  #pragma unroll
  for(int c4=0; c4<16; c4++){
    float4 v;
    v.x = xb[(4*c4+0)*NP + n];
    v.y = xb[(4*c4+1)*NP + n];
    v.z = xb[(4*c4+2)*NP + n];
    v.w = xb[(4*c4+3)*NP + n];
    s += v.x*v.x + v.y*v.y + v.z*v.z + v.w*v.w;
    f4[c4] = v;
  }
  g_sq[b*NP+n] = s;
}

// ---------------- fused Gram + top-20 (scalar v2) ----------------
// vs R2: separate sD buffer -> 2 barriers/iter (was 4); selection uses a single
// combined ballot with the candidate walk + worst-recompute gated on it.
__global__ __launch_bounds__(256) void k_knn(){
  __shared__ float sA[64][68];
  __shared__ float sB[64][68];
  __shared__ float sD[64][68];
  __shared__ float sqr[64];
  __shared__ float sqc[64];

  int t = threadIdx.x;
  int lane = t & 31, warp = t >> 5;
  int b = blockIdx.y;
  int rbase = blockIdx.x*64;

  {
    int r = t>>2, cq = (t&3)*4;
    const float4* fr = reinterpret_cast<const float4*>(g_f) + (b*NP + rbase + r)*16;
    #pragma unroll
    for(int j=0;j<4;j++){
      float4 v = fr[cq+j];
      int c = (cq+j)*4;
      sA[c+0][r]=v.x; sA[c+1][r]=v.y; sA[c+2][r]=v.z; sA[c+3][r]=v.w;
    }
    if(t < 64) sqr[t] = g_sq[b*NP + rbase + t];
  }

  float kd[8]; int ki[8]; float worst[8];
  const float INF = __int_as_float(0x7f800000);
  #pragma unroll
  for(int j=0;j<8;j++){ kd[j]=INF; ki[j]=0; worst[j]=INF; }

  int ty = t>>4, tx = t&15;

  for(int ct=0; ct<NP/64; ct++){
    // load B tile (writes sB, sqc; prior gemm reads of sB/sqc are behind syncB(ct-1))
    {
      int r = t>>2, cq = (t&3)*4;
      const float4* fr = reinterpret_cast<const float4*>(g_f) + (b*NP + ct*64 + r)*16;
      #pragma unroll
      for(int j=0;j<4;j++){
        float4 v = fr[cq+j];
        int c = (cq+j)*4;
        sB[c+0][r]=v.x; sB[c+1][r]=v.y; sB[c+2][r]=v.z; sB[c+3][r]=v.w;
      }
      if(t < 64) sqc[t] = g_sq[b*NP + ct*64 + t];
    }
    __syncthreads();   // A: sB/sqc ready; also fences prev selection's sD reads vs this iter's sD writes

    float acc[4][4];
    #pragma unroll
    for(int i=0;i<4;i++)
      #pragma unroll
      for(int j=0;j<4;j++) acc[i][j]=0.f;
    #pragma unroll 4
    for(int c=0;c<64;c++){
      float4 a = *reinterpret_cast<const float4*>(&sA[c][ty*4]);
      float4 w = *reinterpret_cast<const float4*>(&sB[c][tx*4]);
      acc[0][0]+=a.x*w.x; acc[0][1]+=a.x*w.y; acc[0][2]+=a.x*w.z; acc[0][3]+=a.x*w.w;
      acc[1][0]+=a.y*w.x; acc[1][1]+=a.y*w.y; acc[1][2]+=a.y*w.z; acc[1][3]+=a.y*w.w;
      acc[2][0]+=a.z*w.x; acc[2][1]+=a.z*w.y; acc[2][2]+=a.z*w.z; acc[2][3]+=a.z*w.w;
      acc[3][0]+=a.w*w.x; acc[3][1]+=a.w*w.y; acc[3][2]+=a.w*w.z; acc[3][3]+=a.w*w.w;
    }
    // dists -> sD (separate buffer, no alias with sB)
    #pragma unroll
    for(int i=0;i<4;i++){
      int r = ty*4 + i;
      float4 d;
      d.x = sqr[r] + sqc[tx*4+0] - 2.f*acc[i][0];
      d.y = sqr[r] + sqc[tx*4+1] - 2.f*acc[i][1];
      d.z = sqr[r] + sqc[tx*4+2] - 2.f*acc[i][2];
      d.w = sqr[r] + sqc[tx*4+3] - 2.f*acc[i][3];
      *reinterpret_cast<float4*>(&sD[r][tx*4]) = d;
    }
    __syncthreads();   // B: sD ready; gemm's sB/sqc reads complete (next load may overwrite)

    int base = ct*64;
    #pragma unroll
    for(int j=0;j<8;j++){
      int r = warp*8 + j;
      float d0 = sD[r][lane];
      float d1 = sD[r][32 + lane];
      float w = worst[j];
      unsigned many = __ballot_sync(FULLMASK, fminf(d0, d1) < w);
      if(many){
        unsigned m0 = __ballot_sync(FULLMASK, d0 < w);
        unsigned m1 = __ballot_sync(FULLMASK, d1 < w);
        while(m0 | m1){
          float cd; int cm;
          if(m0){ int src=__ffs(m0)-1; m0 &= m0-1; cd=__shfl_sync(FULLMASK,d0,src); cm=base+src; }
          else  { int src=__ffs(m1)-1; m1 &= m1-1; cd=__shfl_sync(FULLMASK,d1,src); cm=base+32+src; }
          float bv = (lane < KNBR) ? kd[j] : -INF;
          int bl = lane;
          #pragma unroll
          for(int off=16; off; off>>=1){
            float ov = __shfl_xor_sync(FULLMASK, bv, off);
            int   ol = __shfl_xor_sync(FULLMASK, bl, off);
            if(ov > bv || (ov == bv && ol < bl)){ bv = ov; bl = ol; }
          }
          if(cd < bv && lane == bl){ kd[j] = cd; ki[j] = cm; }
        }
        float bv = (lane < KNBR) ? kd[j] : -INF;
        #pragma unroll
        for(int off=16; off; off>>=1) bv = fmaxf(bv, __shfl_xor_sync(FULLMASK, bv, off));
        worst[j] = bv;
      }
    }
  }

  #pragma unroll
  for(int j=0;j<8;j++){
    int r = warp*8 + j;
    if(lane < KNBR) g_idx[(b*NP + rbase + r)*KNBR + lane] = ki[j];
  }
}

// ---------------- P = f.W1a^T (which=0), Q = f.W1d^T (which=1) ----------------
__global__ __launch_bounds__(256) void k_gemm64(int which){
  __shared__ float sA[64][68];
  __shared__ float sW[64][68];
  const float* __restrict__ Wm = which ? g_W1d : g_W1a;
  float* __restrict__ Out = which ? g_Q : g_P;
  int t = threadIdx.x;
  int b = blockIdx.y; int rbase = blockIdx.x*64;
  {
    int r = t>>2, cq = (t&3)*4;
    const float4* fr = reinterpret_cast<const float4*>(g_f) + (b*NP + rbase + r)*16;
    #pragma unroll
    for(int j=0;j<4;j++){
      float4 v = fr[cq+j];
      int c = (cq+j)*4;
      sA[c+0][r]=v.x; sA[c+1][r]=v.y; sA[c+2][r]=v.z; sA[c+3][r]=v.w;
    }
  }
  for(int i=t;i<4096;i+=256){ int o=i>>6, c=i&63; sW[c][o] = Wm[o*64+c]; }
  __syncthreads();
  int ty=t>>4, tx=t&15;
  float acc[4][4];
  #pragma unroll
  for(int i=0;i<4;i++)
    #pragma unroll
    for(int j=0;j<4;j++) acc[i][j]=0.f;
  #pragma unroll 4
  for(int c=0;c<64;c++){
    float4 a = *reinterpret_cast<const float4*>(&sA[c][ty*4]);
    float4 w = *reinterpret_cast<const float4*>(&sW[c][tx*4]);
    acc[0][0]+=a.x*w.x; acc[0][1]+=a.x*w.y; acc[0][2]+=a.x*w.z; acc[0][3]+=a.x*w.w;
    acc[1][0]+=a.y*w.x; acc[1][1]+=a.y*w.y; acc[1][2]+=a.y*w.z; acc[1][3]+=a.y*w.w;
    acc[2][0]+=a.z*w.x; acc[2][1]+=a.z*w.y; acc[2][2]+=a.z*w.z; acc[2][3]+=a.z*w.w;
    acc[3][0]+=a.w*w.x; acc[3][1]+=a.w*w.y; acc[3][2]+=a.w*w.z; acc[3][3]+=a.w*w.w;
  }
  float4* O4 = reinterpret_cast<float4*>(Out) + (b*NP + rbase)*16;
  #pragma unroll
  for(int i=0;i<4;i++)
    O4[(ty*4+i)*16 + tx] = make_float4(acc[i][0],acc[i][1],acc[i][2],acc[i][3]);
}

// ---------------- BN1 stats over h1 = P[m]+Q[n] ----------------
__global__ __launch_bounds__(256) void k_stats1(){
  __shared__ float r1[4][64];
  __shared__ float r2[4][64];
  int t = threadIdx.x;
  int o = t & 63, sub = t >> 6;
  int base = blockIdx.x * 512;
  float s1 = 0.f, s2 = 0.f;
  for(int i = sub; i < 512; i += 4){
    int s = base + i;
    int bn = s / KNBR;
    int b = bn >> 13;
    int m = g_idx[s];
    float h = g_P[((b<<13)+m)*64 + o] + g_Q[bn*64 + o];
    s1 += h; s2 += h*h;
  }
  r1[sub][o] = s1; r2[sub][o] = s2;
  __syncthreads();
  if(sub == 0){
    atomicAdd(&g_stats1[o],    r1[0][o]+r1[1][o]+r1[2][o]+r1[3][o]);
    atomicAdd(&g_stats1[64+o], r2[0][o]+r2[1][o]+r2[2][o]+r2[3][o]);
  }
}

// ---------------- BN finalize (0->BN1, 1->BN2) ----------------
__global__ void k_bnfin(const float* __restrict__ g, const float* __restrict__ bb, int which){
  int o = threadIdx.x;
  const float* stats = which ? g_stats2 : g_stats1;
  const float inv = 1.f/(float)NSAMP;
  float mu  = stats[o]*inv;
  float var = stats[64+o]*inv - mu*mu;
  float rstd = rsqrtf(var + 1e-5f);
  float sc = g[o]*rstd;
  if(which){ g_scale2[o]=sc; g_shift2[o]=bb[o]-mu*sc; }
  else     { g_scale1[o]=sc; g_shift1[o]=bb[o]-mu*sc; }
}

// ---------------- conv2 + BN2 stats + max/min over k ----------------
#define PTS_PER 16
__global__ __launch_bounds__(256) void k_conv2(const float* __restrict__ W2){
  __shared__ float sA[64][68];
  __shared__ float sW[64][68];
  __shared__ float sScale[64], sShift[64];
  __shared__ float r1[4][64];
  __shared__ float r2[4][64];
  int t = threadIdx.x;
  const float INF = __int_as_float(0x7f800000);

  for(int i=t;i<4096;i+=256){ int o=i>>6, c=i&63; sW[c][o] = W2[o*64+c]; }
  if(t < 64){ sScale[t]=g_scale1[t]; sShift[t]=g_shift1[t]; }

  float ls1 = 0.f, ls2 = 0.f;
  float rmax[4], rmin[4];
  #pragma unroll
  for(int q=0;q<4;q++){ rmax[q]=-INF; rmin[q]=INF; }

  int ty=t>>4, tx=t&15;
  int myo = t & 63;
  int Sbase = blockIdx.x * (PTS_PER*KNBR);
  int pbase = blockIdx.x * PTS_PER;
  float* sH = &sA[0][0];

  for(int st=0; st<5; st++){
    __syncthreads();
    {
      int sl = t>>2, cq = (t&3)*4;
      int s = Sbase + st*64 + sl;
      int bn = s / KNBR;
      int b = bn >> 13;
      int m = g_idx[s];
      const float4* Pm = reinterpret_cast<const float4*>(g_P) + ((b<<13)+m)*16;
      const float4* Qn = reinterpret_cast<const float4*>(g_Q) + bn*16;
      #pragma unroll
      for(int j=0;j<4;j++){
        int cc = (cq+j)*4;
        float4 p = Pm[cq+j]; float4 q = Qn[cq+j];
        float v0=(p.x+q.x)*sScale[cc+0]+sShift[cc+0]; v0 = v0>=0.f? v0 : 0.2f*v0;
        float v1=(p.y+q.y)*sScale[cc+1]+sShift[cc+1]; v1 = v1>=0.f? v1 : 0.2f*v1;
        float v2=(p.z+q.z)*sScale[cc+2]+sShift[cc+2]; v2 = v2>=0.f? v2 : 0.2f*v2;
        float v3=(p.w+q.w)*sScale[cc+3]+sShift[cc+3]; v3 = v3>=0.f? v3 : 0.2f*v3;
        sA[cc+0][sl]=v0; sA[cc+1][sl]=v1; sA[cc+2][sl]=v2; sA[cc+3][sl]=v3;
      }
    }
    __syncthreads();

    float acc[4][4];
    #pragma unroll
    for(int i=0;i<4;i++)
      #pragma unroll
      for(int j=0;j<4;j++) acc[i][j]=0.f;
    #pragma unroll 4
    for(int c=0;c<64;c++){
      float4 a = *reinterpret_cast<const float4*>(&sA[c][ty*4]);
      float4 w = *reinterpret_cast<const float4*>(&sW[c][tx*4]);
      acc[0][0]+=a.x*w.x; acc[0][1]+=a.x*w.y; acc[0][2]+=a.x*w.z; acc[0][3]+=a.x*w.w;
      acc[1][0]+=a.y*w.x; acc[1][1]+=a.y*w.y; acc[1][2]+=a.y*w.z; acc[1][3]+=a.y*w.w;
      acc[2][0]+=a.z*w.x; acc[2][1]+=a.z*w.y; acc[2][2]+=a.z*w.z; acc[2][3]+=a.z*w.w;
      acc[3][0]+=a.w*w.x; acc[3][1]+=a.w*w.y; acc[3][2]+=a.w*w.z; acc[3][3]+=a.w*w.w;
    }
    __syncthreads();
    #pragma unroll
    for(int i=0;i<4;i++)
      #pragma unroll
      for(int j=0;j<4;j++)
        sH[(tx*4+j)*68 + ty*4+i] = acc[i][j];
    __syncthreads();
    #pragma unroll
    for(int q=0;q<4;q++){
      int p = (t>>6) + q*4;
      int s0 = p*KNBR - st*64;
      int s1e = s0 + KNBR;
      if(s0 < 0) s0 = 0;
      if(s1e > 64) s1e = 64;
      float mx = rmax[q], mn = rmin[q];
      for(int s=s0; s<s1e; s++){
        float v = sH[myo*68 + s];
        ls1 += v; ls2 += v*v;
        mx = fmaxf(mx, v); mn = fminf(mn, v);
      }
      rmax[q] = mx; rmin[q] = mn;
    }
  }

  #pragma unroll
  for(int q=0;q<4;q++){
    int p = (t>>6) + q*4;
    g_gmax[(pbase+p)*64 + myo] = rmax[q];
    g_gmin[(pbase+p)*64 + myo] = rmin[q];
  }
  r1[t>>6][myo] = ls1;
  r2[t>>6][myo] = ls2;
  __syncthreads();
  if(t < 64){
    atomicAdd(&g_stats2[t],    r1[0][t]+r1[1][t]+r1[2][t]+r1[3][t]);
    atomicAdd(&g_stats2[64+t], r2[0][t]+r2[1][t]+r2[2][t]+r2[3][t]);
  }
}

// ---------------- output: BN2 + lrelu + transpose ----------------
__global__ void k_out(float* __restrict__ out){
  int n = blockIdx.x*256 + threadIdx.x;
  int o = blockIdx.y, b = blockIdx.z;
  float s = g_scale2[o], tsh = g_shift2[o];
  const float* src = (s >= 0.f) ? g_gmax : g_gmin;
  float v = src[(b*NP + n)*64 + o];
  float h = s*v + tsh;
  out[(b*64 + o)*NP + n] = (h >= 0.f) ? h : 0.2f*h;
}

extern "C" void kernel_launch(void* const* d_in, const int* in_sizes, int n_in,
                              void* d_out, int out_size){
  const float* x  = (const float*)d_in[0];
  const float* W1 = (const float*)d_in[1];
  const float* g1 = (const float*)d_in[2];
  const float* b1 = (const float*)d_in[3];
  const float* W2 = (const float*)d_in[4];
  const float* g2 = (const float*)d_in[5];
  const float* b2 = (const float*)d_in[6];
  float* out = (float*)d_out;

  k_prep<<<64, 64>>>(W1);
  k_transpose<<<dim3(NP/256, NB), 256>>>(x);
  k_gemm64<<<dim3(NP/64, NB), 256>>>(0);
  k_knn<<<dim3(NP/64, NB), 256>>>();
  k_gemm64<<<dim3(NP/64, NB), 256>>>(1);
  k_stats1<<<NSAMP/512, 256>>>();
  k_bnfin<<<1, 64>>>(g1, b1, 0);
  k_conv2<<<NPT/PTS_PER, 256>>>(W2);
  k_bnfin<<<1, 64>>>(g2, b2, 1);
  k_out<<<dim3(NP/256, 64, NB), 256>>>(out);
}